// round 6
// baseline (speedup 1.0000x reference)
#include <cuda_runtime.h>
#include <cstdint>

#define NTOK 16384
#define DK   256
#define MC   1024
#define BV   32
#define COMMITC 0.25f
#define DECAYC  0.99f
#define EPSC    1e-5f
#define TEMPC   0.1f
#define LOGM    6.931471805599453f   /* ln(1024) */

// -------- static device scratch (no allocations allowed) --------
__device__ float g_S[2][NTOK][MC];       // dot-product scratch (reused both phases)
__device__ float g_xsq[2][NTOK];
__device__ float g_esq[MC];
__device__ int   g_idx[2][NTOK];         // [0]=a_idx, [1]=v_idx
__device__ float g_adj[2][NTOK];
__device__ float g_cnt[2][MC];           // [0]=c_v, [1]=c_a
__device__ float g_wsum[2][MC][DK];      // [0]=S_v, [1]=S_a
__device__ float g_ec[MC];
__device__ float g_en[MC][DK];
__device__ float g_loss;

// -------- packed f32x2 helpers (Blackwell FFMA2) --------
__device__ __forceinline__ unsigned long long ffma2(unsigned long long a,
                                                    unsigned long long b,
                                                    unsigned long long c) {
    unsigned long long d;
    asm("fma.rn.f32x2 %0, %1, %2, %3;" : "=l"(d) : "l"(a), "l"(b), "l"(c));
    return d;
}
__device__ __forceinline__ unsigned long long dup2(float x) {
    unsigned long long d;
    asm("mov.b64 %0, {%1, %1};" : "=l"(d) : "f"(x), "f"(x));
    return d;
}

// -------- zero accumulators (must run every launch for graph replay) --------
__global__ void k_zero() {
    unsigned i = blockIdx.x * blockDim.x + threadIdx.x;
    if (i < 2u * MC * DK) ((float*)g_wsum)[i] = 0.f;
    if (i < 2u * MC)      ((float*)g_cnt)[i]  = 0.f;
    if (i == 0)           g_loss = 0.f;
}

// -------- row squared norms: embedding rows then audio/video rows --------
__global__ void k_sq(const float* __restrict__ a, const float* __restrict__ v,
                     const float* __restrict__ e) {
    __shared__ float sb[256];
    int bid = blockIdx.x, t = threadIdx.x;
    const float* src; float* dst;
    if (bid < MC) { src = e + (size_t)bid * DK; dst = &g_esq[bid]; }
    else {
        int idx = bid - MC;
        int z = idx / NTOK, r = idx % NTOK;
        src = (z ? v : a) + (size_t)r * DK;
        dst = &g_xsq[z][r];
    }
    float x = src[t];
    sb[t] = x * x; __syncthreads();
    for (int o = 128; o > 0; o >>= 1) { if (t < o) sb[t] += sb[t + o]; __syncthreads(); }
    if (t == 0) *dst = sb[0];
}

// -------- NT GEMM: g_S[z] = X_z [NTOK,DK] @ Bm[MC,DK]^T --------
// 128x128x32 tile, 256 threads, 8x8 per thread via packed f32x2 FFMA.
__global__ void __launch_bounds__(256, 2)
k_gemm(const float* __restrict__ A0, const float* __restrict__ A1,
       const float* __restrict__ BmParam, int use_en) {
    __shared__ float As[32][128];
    __shared__ float Bs[32][128];
    const int z = blockIdx.z;
    const float* A  = z ? A1 : A0;
    const float* Bm = use_en ? &g_en[0][0] : BmParam;
    float* C = &g_S[0][0][0] + (size_t)z * NTOK * MC;
    const int bm = blockIdx.y * 128;
    const int bn = blockIdx.x * 128;
    const int t  = threadIdx.x;
    const int tx = t & 15, ty = t >> 4;
    const int lk = t & 7,  lr = t >> 3;   // lr in 0..31

    unsigned long long acc[8][4];
#pragma unroll
    for (int i = 0; i < 8; i++)
#pragma unroll
        for (int j = 0; j < 4; j++) acc[i][j] = 0ull;

    for (int k0 = 0; k0 < DK; k0 += 32) {
#pragma unroll
        for (int it = 0; it < 4; ++it) {
            int r = lr + 32 * it;
            float4 va = *(const float4*)(A  + (size_t)(bm + r) * DK + k0 + lk * 4);
            As[lk * 4 + 0][r] = va.x; As[lk * 4 + 1][r] = va.y;
            As[lk * 4 + 2][r] = va.z; As[lk * 4 + 3][r] = va.w;
            float4 vb = *(const float4*)(Bm + (size_t)(bn + r) * DK + k0 + lk * 4);
            Bs[lk * 4 + 0][r] = vb.x; Bs[lk * 4 + 1][r] = vb.y;
            Bs[lk * 4 + 2][r] = vb.z; Bs[lk * 4 + 3][r] = vb.w;
        }
        __syncthreads();
#pragma unroll
        for (int kk = 0; kk < 32; ++kk) {
            const float4 a0 = *(const float4*)&As[kk][ty * 8];
            const float4 a1 = *(const float4*)&As[kk][ty * 8 + 4];
            const ulonglong2 b0 = *(const ulonglong2*)&Bs[kk][tx * 8];
            const ulonglong2 b1 = *(const ulonglong2*)&Bs[kk][tx * 8 + 4];
            unsigned long long bb0 = b0.x, bb1 = b0.y, bb2 = b1.x, bb3 = b1.y;
            float av[8] = {a0.x, a0.y, a0.z, a0.w, a1.x, a1.y, a1.z, a1.w};
#pragma unroll
            for (int i = 0; i < 8; i++) {
                unsigned long long ad = dup2(av[i]);
                acc[i][0] = ffma2(ad, bb0, acc[i][0]);
                acc[i][1] = ffma2(ad, bb1, acc[i][1]);
                acc[i][2] = ffma2(ad, bb2, acc[i][2]);
                acc[i][3] = ffma2(ad, bb3, acc[i][3]);
            }
        }
        __syncthreads();
    }
#pragma unroll
    for (int i = 0; i < 8; i++) {
        size_t off = (size_t)(bm + ty * 8 + i) * MC + bn + tx * 8;
        *(ulonglong2*)(C + off)     = make_ulonglong2(acc[i][0], acc[i][1]);
        *(ulonglong2*)(C + off + 4) = make_ulonglong2(acc[i][2], acc[i][3]);
    }
}

// -------- phase-1 row pass: argmin(dist), entropy adjustment --------
__global__ void k_row1() {
    __shared__ float sred[256];
    __shared__ int   sidx[256];
    int row = blockIdx.x, z = blockIdx.y, t = threadIdx.x;
    const float* Srow = &g_S[z][row][0];
    float xs = g_xsq[z][row];

    float sv[4];
    float bestv = -1e30f; int besti = MC;
#pragma unroll
    for (int q = 0; q < 4; q++) {
        int m = q * 256 + t;
        float d = xs + g_esq[m] - 2.f * Srow[m];
        float s = -sqrtf(fmaxf(d, 0.f));
        sv[q] = s;
        if (s > bestv) { bestv = s; besti = m; }   // m ascending -> first-index kept
    }
    sred[t] = bestv; sidx[t] = besti; __syncthreads();
    for (int o = 128; o > 0; o >>= 1) {
        if (t < o) {
            float ov = sred[t + o]; int oi = sidx[t + o];
            if (ov > sred[t] || (ov == sred[t] && oi < sidx[t])) { sred[t] = ov; sidx[t] = oi; }
        }
        __syncthreads();
    }
    float rmax = sred[0]; int am = sidx[0]; __syncthreads();

    float eq[4], es = 0.f;
#pragma unroll
    for (int q = 0; q < 4; q++) { eq[q] = __expf(sv[q] - rmax); es += eq[q]; }
    sred[t] = es; __syncthreads();
    for (int o = 128; o > 0; o >>= 1) { if (t < o) sred[t] += sred[t + o]; __syncthreads(); }
    float invZ = 1.f / sred[0]; __syncthreads();

    float ent = 0.f;
#pragma unroll
    for (int q = 0; q < 4; q++) { float p = eq[q] * invZ; ent += p * __logf(p + 1e-5f); }
    sred[t] = ent; __syncthreads();
    for (int o = 128; o > 0; o >>= 1) { if (t < o) sred[t] += sred[t + o]; __syncthreads(); }
    if (t == 0) {
        float H = -sred[0];
        g_adj[z][row] = 1.f - H * (1.f / LOGM);
        g_idx[z][row] = am;
    }
}

// -------- EMA scatter: counts + weighted (a+v) sums --------
__global__ void k_scatter(const float* __restrict__ a, const float* __restrict__ v) {
    int row = blockIdx.x, t = threadIdx.x;
    int   ai = g_idx[0][row], vi = g_idx[1][row];
    float aadj = g_adj[0][row], vadj = g_adj[1][row];
    float tv = a[(size_t)row * DK + t] + v[(size_t)row * DK + t];
    atomicAdd(&g_wsum[0][vi][t], vadj * tv);   // video-driven pass
    atomicAdd(&g_wsum[1][ai][t], aadj * tv);   // audio-driven pass
    if (t == 0) {
        atomicAdd(&g_cnt[0][vi], vadj);
        atomicAdd(&g_cnt[1][ai], aadj);
    }
}

// -------- sequential EMA count normalization (1 block, M threads) --------
__global__ void k_ec(const float* __restrict__ ema_count) {
    __shared__ float sb[MC];
    int t = threadIdx.x;
    float ec = DECAYC * ema_count[t] + (1.f - DECAYC) * g_cnt[0][t];
    sb[t] = ec; __syncthreads();
    for (int o = 512; o > 0; o >>= 1) { if (t < o) sb[t] += sb[t + o]; __syncthreads(); }
    float n1 = sb[0]; __syncthreads();
    ec = (ec + EPSC) / (n1 + MC * EPSC) * n1;
    ec = DECAYC * ec + (1.f - DECAYC) * g_cnt[1][t];
    sb[t] = ec; __syncthreads();
    for (int o = 512; o > 0; o >>= 1) { if (t < o) sb[t] += sb[t + o]; __syncthreads(); }
    float n2 = sb[0]; __syncthreads();
    g_ec[t] = (ec + EPSC) / (n2 + MC * EPSC) * n2;
}

// -------- build normalized new codebook g_en --------
__global__ void k_en(const float* __restrict__ ema_weight) {
    __shared__ float sb[256];
    int m = blockIdx.x, t = threadIdx.x;
    float ew = (DECAYC * DECAYC) * ema_weight[(size_t)m * DK + t]
             + DECAYC * 0.5f * (1.f - DECAYC) * g_wsum[0][m][t]
             + 0.5f * (1.f - DECAYC) * g_wsum[1][m][t];
    float emb = ew / g_ec[m];
    sb[t] = emb * emb; __syncthreads();
    for (int o = 128; o > 0; o >>= 1) { if (t < o) sb[t] += sb[t + o]; __syncthreads(); }
    float nrm = sqrtf(sb[0]);
    g_en[m][t] = emb / fmaxf(nrm, 1e-8f);
}

// -------- phase-2 row pass: logsumexp + picked logits -> loss --------
__global__ void k_row2() {
    __shared__ float sred[256];
    __shared__ float spick[2];
    int row = blockIdx.x, z = blockIdx.y, t = threadIdx.x;
    const float* Srow = &g_S[z][row][0];
    float xs = g_xsq[z][row];
    float scale = 1.f / (fmaxf(sqrtf(xs), 1e-8f) * TEMPC);
    int self  = g_idx[z][row];
    int cross = g_idx[1 - z][row];

    float l[4], mx = -1e30f;
#pragma unroll
    for (int q = 0; q < 4; q++) {
        int m = q * 256 + t;
        l[q] = Srow[m] * scale;
        mx = fmaxf(mx, l[q]);
        if (m == self)  spick[0] = l[q];
        if (m == cross) spick[1] = l[q];
    }
    sred[t] = mx; __syncthreads();
    for (int o = 128; o > 0; o >>= 1) { if (t < o) sred[t] = fmaxf(sred[t], sred[t + o]); __syncthreads(); }
    float rmax = sred[0]; __syncthreads();
    float es = 0.f;
#pragma unroll
    for (int q = 0; q < 4; q++) es += __expf(l[q] - rmax);
    sred[t] = es; __syncthreads();
    for (int o = 128; o > 0; o >>= 1) { if (t < o) sred[t] += sred[t + o]; __syncthreads(); }
    if (t == 0) {
        float lse = __logf(sred[0]) + rmax;
        float contrib = lse - COMMITC * spick[0] - (1.f - COMMITC) * spick[1];
        atomicAdd(&g_loss, contrib);
    }
}

__global__ void k_final(float* __restrict__ out) {
    out[0] = COMMITC * g_loss / ((float)NTOK * (float)BV);
}

extern "C" void kernel_launch(void* const* d_in, const int* in_sizes, int n_in,
                              void* d_out, int out_size) {
    const float* audio      = (const float*)d_in[0];
    const float* video      = (const float*)d_in[1];
    const float* emb        = (const float*)d_in[2];
    const float* ema_count  = (const float*)d_in[3];
    const float* ema_weight = (const float*)d_in[4];
    float* out = (float*)d_out;

    k_zero<<<2048, 256>>>();
    k_sq<<<MC + 2 * NTOK, 256>>>(audio, video, emb);

    dim3 gg(MC / 128, NTOK / 128, 2);
    k_gemm<<<gg, 256>>>(audio, video, emb, 0);          // dist dots vs old codebook
    k_row1<<<dim3(NTOK, 2), 256>>>();
    k_scatter<<<NTOK, 256>>>(audio, video);
    k_ec<<<1, MC>>>(ema_count);
    k_en<<<MC, 256>>>(ema_weight);
    k_gemm<<<gg, 256>>>(audio, video, emb, 1);          // logits dots vs new codebook
    k_row2<<<dim3(NTOK, 2), 256>>>();
    k_final<<<1, 1>>>(out);
}

// round 8
// speedup vs baseline: 2.6454x; 2.6454x over previous
#include <cuda_runtime.h>
#include <cuda_bf16.h>
#include <cstdint>

#define NTOK 16384
#define DK   256
#define MC   1024
#define KD   768            /* split-K: [hi | hi/lo | lo/hi] */
#define BV   32
#define COMMITC 0.25f
#define DECAYC  0.99f
#define EPSC    1e-5f
#define TEMPC   0.1f
#define LOGM    6.931471805599453f   /* ln(1024) */

// ---------------- static device scratch ----------------
__device__ float g_S[2][NTOK][MC];            // dot scratch (both phases)
__device__ __nv_bfloat16 g_Abf[2][NTOK][KD];  // split A (audio/video), reused both phases
__device__ __nv_bfloat16 g_Bbf[MC][KD];       // split B (emb, then en)
__device__ float g_xsq[2][NTOK];
__device__ float g_esq[MC];
__device__ int   g_idx[2][NTOK];
__device__ float g_adj[2][NTOK];
__device__ float g_cnt[2][MC];
__device__ float g_wsum[2][MC][DK];
__device__ float g_ec[MC];
__device__ float g_en[MC][DK];
__device__ float g_loss;

// ---------------- PTX helpers (sm_80-family only; no arch-'a' features) ----------------
__device__ __forceinline__ uint32_t smem_u32(const void* p) {
    uint32_t a;
    asm("{ .reg .u64 t; cvta.to.shared.u64 t, %1; cvt.u32.u64 %0, t; }" : "=r"(a) : "l"(p));
    return a;
}
#define CP_ASYNC16(dst, src) \
    asm volatile("cp.async.cg.shared.global [%0], [%1], 16;" :: "r"(dst), "l"(src) : "memory")
#define CP_COMMIT() asm volatile("cp.async.commit_group;" ::: "memory")
#define CP_WAIT(n)  asm volatile("cp.async.wait_group %0;" :: "n"(n) : "memory")

__device__ __forceinline__ void ldsm_x4(uint32_t* r, uint32_t addr) {
    asm volatile("ldmatrix.sync.aligned.m8n8.x4.shared.b16 {%0,%1,%2,%3}, [%4];"
        : "=r"(r[0]), "=r"(r[1]), "=r"(r[2]), "=r"(r[3]) : "r"(addr));
}
__device__ __forceinline__ void mma16816(float* d, const uint32_t* a,
                                         uint32_t b0, uint32_t b1) {
    asm volatile("mma.sync.aligned.m16n8k16.row.col.f32.bf16.bf16.f32 "
        "{%0,%1,%2,%3}, {%4,%5,%6,%7}, {%8,%9}, {%0,%1,%2,%3};"
        : "+f"(d[0]), "+f"(d[1]), "+f"(d[2]), "+f"(d[3])
        : "r"(a[0]), "r"(a[1]), "r"(a[2]), "r"(a[3]), "r"(b0), "r"(b1));
}

// ---------------- zero accumulators ----------------
__global__ void k_zero() {
    unsigned i = blockIdx.x * blockDim.x + threadIdx.x;
    if (i < 2u * MC * DK) ((float*)g_wsum)[i] = 0.f;
    if (i < 2u * MC)      ((float*)g_cnt)[i]  = 0.f;
    if (i == 0)           g_loss = 0.f;
}

// ---------------- prep A: hi/lo split + row squared norm ----------------
__global__ void k_prepA(const float* __restrict__ a, const float* __restrict__ v) {
    int row = blockIdx.x, z = blockIdx.y, t = threadIdx.x;
    int lane = t & 31, w = t >> 5;
    const float* src = (z ? v : a) + (size_t)row * DK;
    float x = src[t];
    __nv_bfloat16 hi = __float2bfloat16(x);
    float lo = x - __bfloat162float(hi);
    g_Abf[z][row][t]       = hi;
    g_Abf[z][row][256 + t] = hi;
    g_Abf[z][row][512 + t] = __float2bfloat16(lo);
    __shared__ float sp[8];
    float s = x * x;
#pragma unroll
    for (int o = 16; o; o >>= 1) s += __shfl_xor_sync(0xFFFFFFFFu, s, o);
    if (lane == 0) sp[w] = s;
    __syncthreads();
    if (t == 0) {
        float acc = 0.f;
#pragma unroll
        for (int i = 0; i < 8; i++) acc += sp[i];
        g_xsq[z][row] = acc;
    }
}

// ---------------- prep B: hi/lo split (+esq for phase 1) ----------------
__global__ void k_prepB(const float* __restrict__ embParam, int use_en) {
    int m = blockIdx.x, t = threadIdx.x;
    int lane = t & 31, w = t >> 5;
    const float* src = use_en ? &g_en[0][0] : embParam;
    float x = src[(size_t)m * DK + t];
    __nv_bfloat16 hi = __float2bfloat16(x);
    float lo = x - __bfloat162float(hi);
    g_Bbf[m][t]       = hi;
    g_Bbf[m][256 + t] = __float2bfloat16(lo);
    g_Bbf[m][512 + t] = hi;
    if (!use_en) {
        __shared__ float sp[8];
        float s = x * x;
#pragma unroll
        for (int o = 16; o; o >>= 1) s += __shfl_xor_sync(0xFFFFFFFFu, s, o);
        if (lane == 0) sp[w] = s;
        __syncthreads();
        if (t == 0) {
            float acc = 0.f;
#pragma unroll
            for (int i = 0; i < 8; i++) acc += sp[i];
            g_esq[m] = acc;
        }
    }
}

// ---------------- HMMA GEMM: g_S[z] = A_bf [NTOK,KD] @ B_bf [MC,KD]^T ----------------
// CTA 128x128, 8 warps (4x2 of 32x64), K chunks of 64, 3-stage cp.async pipeline.
#define BM 128
#define BN 128
#define BK 64
#define NCH (KD / BK)                 /* 12 */
#define STAGE (BM * BK * 2 + BN * BK * 2)  /* 32768 */
#define NSTAGE 3
#define SMEMSZ (NSTAGE * STAGE)       /* 98304 */

__global__ void __launch_bounds__(256, 2) k_mma() {
    extern __shared__ char sm[];
    const uint32_t sb = smem_u32(sm);
    const int t = threadIdx.x, lane = t & 31, w = t >> 5;
    const int z = blockIdx.z;
    const int bm = blockIdx.y * BM, bn = blockIdx.x * BN;
    const __nv_bfloat16* Ag = &g_Abf[z][bm][0];
    const __nv_bfloat16* Bg = &g_Bbf[bn][0];

    float acc[2][8][4];
#pragma unroll
    for (int i = 0; i < 2; i++)
#pragma unroll
        for (int j = 0; j < 8; j++)
#pragma unroll
            for (int k = 0; k < 4; k++) acc[i][j][k] = 0.f;

    // global->smem stage loader: 128 rows x 64 bf16 (128B rows) for A and B,
    // 16B-block XOR swizzle (phys_blk = blk ^ (row&7)) for conflict-free ldmatrix.
    auto load_stage = [&](int s, int c) {
        uint32_t ab = sb + s * STAGE;
        uint32_t bb = ab + BM * BK * 2;
#pragma unroll
        for (int j = 0; j < 4; ++j) {
            int idx = t + j * 256, row = idx >> 3, blk = idx & 7;
            CP_ASYNC16(ab + row * 128 + 16 * (blk ^ (row & 7)),
                       Ag + (size_t)row * KD + c * BK + blk * 8);
        }
#pragma unroll
        for (int j = 0; j < 4; ++j) {
            int idx = t + j * 256, row = idx >> 3, blk = idx & 7;
            CP_ASYNC16(bb + row * 128 + 16 * (blk ^ (row & 7)),
                       Bg + (size_t)row * KD + c * BK + blk * 8);
        }
        CP_COMMIT();
    };

    load_stage(0, 0);
    load_stage(1, 1);

    const int wm = w >> 1, wn = w & 1;
    const uint32_t swz = (uint32_t)(lane & 7) << 4;
    const uint32_t kh  = (uint32_t)(lane & 16);
    const uint32_t rA  = wm * 32 + (lane & 15);
    const uint32_t rB  = wn * 64 + (lane & 15);

    for (int c = 0; c < NCH; ++c) {
        if (c == NCH - 1) { CP_WAIT(0); } else { CP_WAIT(1); }
        __syncthreads();
        if (c + 2 < NCH) load_stage((c + 2) % NSTAGE, c + 2);

        uint32_t ab = sb + (c % NSTAGE) * STAGE;
        uint32_t bb = ab + BM * BK * 2;
#pragma unroll
        for (int ks = 0; ks < 4; ++ks) {
            uint32_t kx = ((uint32_t)(ks * 32) + kh) ^ swz;
            uint32_t A0[4], A1[4];
            ldsm_x4(A0, ab + rA * 128 + kx);
            ldsm_x4(A1, ab + (rA + 16) * 128 + kx);
#pragma unroll
            for (int q = 0; q < 4; ++q) {
                uint32_t Bf[4];
                ldsm_x4(Bf, bb + (rB + q * 16) * 128 + kx);
                mma16816(acc[0][2 * q],     A0, Bf[0], Bf[2]);
                mma16816(acc[0][2 * q + 1], A0, Bf[1], Bf[3]);
                mma16816(acc[1][2 * q],     A1, Bf[0], Bf[2]);
                mma16816(acc[1][2 * q + 1], A1, Bf[1], Bf[3]);
            }
        }
    }

    // epilogue: c0,c1 at (row = lane>>2, col = 2*(lane&3)); c2,c3 at row+8
    float* C = &g_S[z][0][0];
#pragma unroll
    for (int mi = 0; mi < 2; ++mi) {
        int r0 = bm + wm * 32 + mi * 16 + (lane >> 2);
#pragma unroll
        for (int j = 0; j < 8; ++j) {
            int col = bn + wn * 64 + j * 8 + (lane & 3) * 2;
            *(float2*)(C + (size_t)r0 * MC + col)       = make_float2(acc[mi][j][0], acc[mi][j][1]);
            *(float2*)(C + (size_t)(r0 + 8) * MC + col) = make_float2(acc[mi][j][2], acc[mi][j][3]);
        }
    }
}

// ---------------- phase-1 row pass: warp per row ----------------
__global__ void k_row1() {
    int t = threadIdx.x, lane = t & 31, w = t >> 5;
    int row = blockIdx.x * 8 + w, z = blockIdx.y;
    const float4* S4 = (const float4*)&g_S[z][row][0];
    const float4* E4 = (const float4*)g_esq;
    float xs = g_xsq[z][row];

    float sv[32];
    float bestv = -1e30f; int besti = MC;
#pragma unroll
    for (int u = 0; u < 8; ++u) {
        float4 s4 = S4[u * 32 + lane];
        float4 e4 = E4[u * 32 + lane];
        int mb = (u * 32 + lane) * 4;
        float ss[4] = {s4.x, s4.y, s4.z, s4.w};
        float ee[4] = {e4.x, e4.y, e4.z, e4.w};
#pragma unroll
        for (int j = 0; j < 4; ++j) {
            float dist = xs + ee[j] - 2.f * ss[j];
            float val = -sqrtf(fmaxf(dist, 0.f));
            sv[u * 4 + j] = val;
            if (val > bestv) { bestv = val; besti = mb + j; }
        }
    }
#pragma unroll
    for (int o = 16; o; o >>= 1) {
        float ov = __shfl_xor_sync(0xFFFFFFFFu, bestv, o);
        int   oi = __shfl_xor_sync(0xFFFFFFFFu, besti, o);
        if (ov > bestv || (ov == bestv && oi < besti)) { bestv = ov; besti = oi; }
    }
    float es = 0.f;
#pragma unroll
    for (int i = 0; i < 32; i++) { sv[i] = __expf(sv[i] - bestv); es += sv[i]; }
#pragma unroll
    for (int o = 16; o; o >>= 1) es += __shfl_xor_sync(0xFFFFFFFFu, es, o);
    float invZ = 1.f / es;
    float ent = 0.f;
#pragma unroll
    for (int i = 0; i < 32; i++) { float p = sv[i] * invZ; ent += p * __logf(p + 1e-5f); }
#pragma unroll
    for (int o = 16; o; o >>= 1) ent += __shfl_xor_sync(0xFFFFFFFFu, ent, o);
    if (lane == 0) {
        g_adj[z][row] = 1.f - (-ent) * (1.f / LOGM);
        g_idx[z][row] = besti;
    }
}

// ---------------- EMA scatter ----------------
__global__ void k_scatter(const float* __restrict__ a, const float* __restrict__ v) {
    int row = blockIdx.x, t = threadIdx.x;
    int   ai = g_idx[0][row], vi = g_idx[1][row];
    float aadj = g_adj[0][row], vadj = g_adj[1][row];
    float tv = a[(size_t)row * DK + t] + v[(size_t)row * DK + t];
    atomicAdd(&g_wsum[0][vi][t], vadj * tv);
    atomicAdd(&g_wsum[1][ai][t], aadj * tv);
    if (t == 0) {
        atomicAdd(&g_cnt[0][vi], vadj);
        atomicAdd(&g_cnt[1][ai], aadj);
    }
}

// ---------------- sequential EMA count normalization ----------------
__global__ void k_ec(const float* __restrict__ ema_count) {
    __shared__ float sb[MC];
    int t = threadIdx.x;
    float ec = DECAYC * ema_count[t] + (1.f - DECAYC) * g_cnt[0][t];
    sb[t] = ec; __syncthreads();
    for (int o = 512; o > 0; o >>= 1) { if (t < o) sb[t] += sb[t + o]; __syncthreads(); }
    float n1 = sb[0]; __syncthreads();
    ec = (ec + EPSC) / (n1 + MC * EPSC) * n1;
    ec = DECAYC * ec + (1.f - DECAYC) * g_cnt[1][t];
    sb[t] = ec; __syncthreads();
    for (int o = 512; o > 0; o >>= 1) { if (t < o) sb[t] += sb[t + o]; __syncthreads(); }
    float n2 = sb[0]; __syncthreads();
    g_ec[t] = (ec + EPSC) / (n2 + MC * EPSC) * n2;
}

// ---------------- normalized new codebook ----------------
__global__ void k_en(const float* __restrict__ ema_weight) {
    __shared__ float sb[256];
    int m = blockIdx.x, t = threadIdx.x;
    float ew = (DECAYC * DECAYC) * ema_weight[(size_t)m * DK + t]
             + DECAYC * 0.5f * (1.f - DECAYC) * g_wsum[0][m][t]
             + 0.5f * (1.f - DECAYC) * g_wsum[1][m][t];
    float emb = ew / g_ec[m];
    sb[t] = emb * emb; __syncthreads();
    for (int o = 128; o > 0; o >>= 1) { if (t < o) sb[t] += sb[t + o]; __syncthreads(); }
    float nrm = sqrtf(sb[0]);
    g_en[m][t] = emb / fmaxf(nrm, 1e-8f);
}

// ---------------- phase-2 row pass: warp per row ----------------
__global__ void k_row2() {
    int t = threadIdx.x, lane = t & 31, w = t >> 5;
    int row = blockIdx.x * 8 + w, z = blockIdx.y;
    const float4* S4 = (const float4*)&g_S[z][row][0];
    float xs = g_xsq[z][row];
    float scale = 1.f / (fmaxf(sqrtf(xs), 1e-8f) * TEMPC);
    int self  = g_idx[z][row];
    int cross = g_idx[1 - z][row];

    float l[32];
    float mx = -1e30f, ps = 0.f, pc = 0.f;
#pragma unroll
    for (int u = 0; u < 8; ++u) {
        float4 s4 = S4[u * 32 + lane];
        int mb = (u * 32 + lane) * 4;
        float vv[4] = {s4.x, s4.y, s4.z, s4.w};
#pragma unroll
        for (int j = 0; j < 4; ++j) {
            float lv = vv[j] * scale;
            l[u * 4 + j] = lv;
            mx = fmaxf(mx, lv);
            if (mb + j == self)  ps = lv;
            if (mb + j == cross) pc = lv;
        }
    }
#pragma unroll
    for (int o = 16; o; o >>= 1) mx = fmaxf(mx, __shfl_xor_sync(0xFFFFFFFFu, mx, o));
    float es = 0.f;
#pragma unroll
    for (int i = 0; i < 32; i++) es += __expf(l[i] - mx);
#pragma unroll
    for (int o = 16; o; o >>= 1) {
        es += __shfl_xor_sync(0xFFFFFFFFu, es, o);
        ps += __shfl_xor_sync(0xFFFFFFFFu, ps, o);
        pc += __shfl_xor_sync(0xFFFFFFFFu, pc, o);
    }
    if (lane == 0) {
        float lse = __logf(es) + mx;
        atomicAdd(&g_loss, lse - COMMITC * ps - (1.f - COMMITC) * pc);
    }
}

__global__ void k_final(float* __restrict__ out) {
    out[0] = COMMITC * g_loss / ((float)NTOK * (float)BV);
}

extern "C" void kernel_launch(void* const* d_in, const int* in_sizes, int n_in,
                              void* d_out, int out_size) {
    const float* audio      = (const float*)d_in[0];
    const float* video      = (const float*)d_in[1];
    const float* emb        = (const float*)d_in[2];
    const float* ema_count  = (const float*)d_in[3];
    const float* ema_weight = (const float*)d_in[4];
    float* out = (float*)d_out;

    static int smem_set = 0;
    if (!smem_set) {
        cudaFuncSetAttribute(k_mma, cudaFuncAttributeMaxDynamicSharedMemorySize, SMEMSZ);
        smem_set = 1;
    }

    k_zero<<<2048, 256>>>();
    k_prepA<<<dim3(NTOK, 2), 256>>>(audio, video);
    k_prepB<<<MC, 256>>>(emb, 0);

    dim3 gg(MC / BN, NTOK / BM, 2);
    k_mma<<<gg, 256, SMEMSZ>>>();                     // dist dots vs old codebook
    k_row1<<<dim3(NTOK / 8, 2), 256>>>();
    k_scatter<<<NTOK, 256>>>(audio, video);
    k_ec<<<1, MC>>>(ema_count);
    k_en<<<MC, 256>>>(ema_weight);
    k_prepB<<<MC, 256>>>(emb, 1);                     // split new codebook g_en
    k_mma<<<gg, 256, SMEMSZ>>>();                     // logits dots vs new codebook
    k_row2<<<dim3(NTOK / 8, 2), 256>>>();
    k_final<<<1, 1>>>(out);
}

// round 9
// speedup vs baseline: 3.5974x; 1.3598x over previous
#include <cuda_runtime.h>
#include <cuda_fp16.h>
#include <cstdint>

#define NTOK 16384
#define DK   256
#define MC   1024
#define BV   32
#define COMMITC 0.25f
#define DECAYC  0.99f
#define EPSC    1e-5f
#define TEMPC   0.1f
#define LOGM    6.931471805599453f   /* ln(1024) */

// ---------------- static device scratch ----------------
__device__ float g_S[2][NTOK][MC];         // dot scratch (both phases)
__device__ __half g_Ah[2][NTOK][DK];       // fp16 hi of A (audio/video); loader wraps K
__device__ __half g_Bh[MC][2 * DK];        // fp16 [hi | lo] of B (emb, then en)
__device__ float g_xsq[2][NTOK];
__device__ float g_esq[MC];
__device__ int   g_idx[2][NTOK];
__device__ float g_adj[2][NTOK];
__device__ float g_cnt[2][MC];
__device__ float g_wsum[2][MC][DK];
__device__ float g_ec[MC];
__device__ float g_en[MC][DK];
__device__ float g_loss;

// ---------------- PTX helpers (sm_80-family only; no arch-'a' features) ----------------
__device__ __forceinline__ uint32_t smem_u32(const void* p) {
    uint32_t a;
    asm("{ .reg .u64 t; cvta.to.shared.u64 t, %1; cvt.u32.u64 %0, t; }" : "=r"(a) : "l"(p));
    return a;
}
#define CP_ASYNC16(dst, src) \
    asm volatile("cp.async.cg.shared.global [%0], [%1], 16;" :: "r"(dst), "l"(src) : "memory")
#define CP_COMMIT() asm volatile("cp.async.commit_group;" ::: "memory")
#define CP_WAIT(n)  asm volatile("cp.async.wait_group %0;" :: "n"(n) : "memory")

__device__ __forceinline__ void ldsm_x4(uint32_t* r, uint32_t addr) {
    asm volatile("ldmatrix.sync.aligned.m8n8.x4.shared.b16 {%0,%1,%2,%3}, [%4];"
        : "=r"(r[0]), "=r"(r[1]), "=r"(r[2]), "=r"(r[3]) : "r"(addr));
}
__device__ __forceinline__ void mma16816(float* d, const uint32_t* a,
                                         uint32_t b0, uint32_t b1) {
    asm volatile("mma.sync.aligned.m16n8k16.row.col.f32.f16.f16.f32 "
        "{%0,%1,%2,%3}, {%4,%5,%6,%7}, {%8,%9}, {%0,%1,%2,%3};"
        : "+f"(d[0]), "+f"(d[1]), "+f"(d[2]), "+f"(d[3])
        : "r"(a[0]), "r"(a[1]), "r"(a[2]), "r"(a[3]), "r"(b0), "r"(b1));
}

// ---------------- zero accumulators ----------------
__global__ void k_zero() {
    unsigned i = blockIdx.x * blockDim.x + threadIdx.x;
    if (i < 2u * MC * DK) ((float*)g_wsum)[i] = 0.f;
    if (i < 2u * MC)      ((float*)g_cnt)[i]  = 0.f;
    if (i == 0)           g_loss = 0.f;
}

// ---------------- prep A: fp16 hi + row squared norm ----------------
__global__ void k_prepA(const float* __restrict__ a, const float* __restrict__ v) {
    int row = blockIdx.x, z = blockIdx.y, t = threadIdx.x;
    int lane = t & 31, w = t >> 5;
    const float* src = (z ? v : a) + (size_t)row * DK;
    float x = src[t];
    g_Ah[z][row][t] = __float2half(x);
    __shared__ float sp[8];
    float s = x * x;
#pragma unroll
    for (int o = 16; o; o >>= 1) s += __shfl_xor_sync(0xFFFFFFFFu, s, o);
    if (lane == 0) sp[w] = s;
    __syncthreads();
    if (t == 0) {
        float acc = 0.f;
#pragma unroll
        for (int i = 0; i < 8; i++) acc += sp[i];
        g_xsq[z][row] = acc;
    }
}

// ---------------- prep B: fp16 hi/lo split (+esq for phase 1) ----------------
__global__ void k_prepB(const float* __restrict__ embParam, int use_en) {
    int m = blockIdx.x, t = threadIdx.x;
    int lane = t & 31, w = t >> 5;
    const float* src = use_en ? &g_en[0][0] : embParam;
    float x = src[(size_t)m * DK + t];
    __half hi = __float2half(x);
    float lo = x - __half2float(hi);
    g_Bh[m][t]       = hi;
    g_Bh[m][256 + t] = __float2half(lo);
    if (!use_en) {
        __shared__ float sp[8];
        float s = x * x;
#pragma unroll
        for (int o = 16; o; o >>= 1) s += __shfl_xor_sync(0xFFFFFFFFu, s, o);
        if (lane == 0) sp[w] = s;
        __syncthreads();
        if (t == 0) {
            float acc = 0.f;
#pragma unroll
            for (int i = 0; i < 8; i++) acc += sp[i];
            g_esq[m] = acc;
        }
    }
}

// ---------------- HMMA GEMM: g_S[z] = A_h [NTOK,256] @ B_h [MC, nch*64]^T ----------------
// A's k-index wraps mod 256 (hi reused for B's lo half). CTA 128x128, 8 warps,
// K chunks of 64, 3-stage cp.async pipeline, XOR-16B smem swizzle.
#define BM 128
#define BN 128
#define BK 64
#define STAGE (BM * BK * 2 + BN * BK * 2)  /* 32768 */
#define NSTAGE 3
#define SMEMSZ (NSTAGE * STAGE)            /* 98304 */

__global__ void __launch_bounds__(256, 2) k_mma(int nch) {
    extern __shared__ char sm[];
    const uint32_t sb = smem_u32(sm);
    const int t = threadIdx.x, lane = t & 31, w = t >> 5;
    const int z = blockIdx.z;
    const int bm = blockIdx.y * BM, bn = blockIdx.x * BN;
    const __half* Ag = &g_Ah[z][bm][0];
    const __half* Bg = &g_Bh[bn][0];

    float acc[2][8][4];
#pragma unroll
    for (int i = 0; i < 2; i++)
#pragma unroll
        for (int j = 0; j < 8; j++)
#pragma unroll
            for (int k = 0; k < 4; k++) acc[i][j][k] = 0.f;

    // global->smem stage loader; phys 16B block = blk ^ (row&7)
    auto load_stage = [&](int s, int c) {
        uint32_t ab = sb + s * STAGE;
        uint32_t bb = ab + BM * BK * 2;
        int ca = (c & 3) * BK;    // A wraps mod 256
        int cb = c * BK;
#pragma unroll
        for (int j = 0; j < 4; ++j) {
            int idx = t + j * 256, row = idx >> 3, blk = idx & 7;
            CP_ASYNC16(ab + row * 128 + 16 * (blk ^ (row & 7)),
                       Ag + (size_t)row * DK + ca + blk * 8);
        }
#pragma unroll
        for (int j = 0; j < 4; ++j) {
            int idx = t + j * 256, row = idx >> 3, blk = idx & 7;
            CP_ASYNC16(bb + row * 128 + 16 * (blk ^ (row & 7)),
                       Bg + (size_t)row * (2 * DK) + cb + blk * 8);
        }
        CP_COMMIT();
    };

    load_stage(0, 0);
    load_stage(1, 1);

    const int wm = w >> 1, wn = w & 1;
    const uint32_t swz = (uint32_t)(lane & 7) << 4;
    const uint32_t kh  = (uint32_t)(lane & 16);
    const uint32_t rA  = wm * 32 + (lane & 15);
    const uint32_t rB  = wn * 64 + (lane & 15);

    for (int c = 0; c < nch; ++c) {
        if (c == nch - 1) { CP_WAIT(0); } else { CP_WAIT(1); }
        __syncthreads();
        if (c + 2 < nch) load_stage((c + 2) % NSTAGE, c + 2);

        uint32_t ab = sb + (c % NSTAGE) * STAGE;
        uint32_t bb = ab + BM * BK * 2;
#pragma unroll
        for (int ks = 0; ks < 4; ++ks) {
            uint32_t kx = ((uint32_t)(ks * 32) + kh) ^ swz;
            uint32_t A0[4], A1[4];
            ldsm_x4(A0, ab + rA * 128 + kx);
            ldsm_x4(A1, ab + (rA + 16) * 128 + kx);
#pragma unroll
            for (int q = 0; q < 4; ++q) {
                uint32_t Bf[4];
                ldsm_x4(Bf, bb + (rB + q * 16) * 128 + kx);
                mma16816(acc[0][2 * q],     A0, Bf[0], Bf[2]);
                mma16816(acc[0][2 * q + 1], A0, Bf[1], Bf[3]);
                mma16816(acc[1][2 * q],     A1, Bf[0], Bf[2]);
                mma16816(acc[1][2 * q + 1], A1, Bf[1], Bf[3]);
            }
        }
        __syncthreads();
    }

    float* C = &g_S[z][0][0];
#pragma unroll
    for (int mi = 0; mi < 2; ++mi) {
        int r0 = bm + wm * 32 + mi * 16 + (lane >> 2);
#pragma unroll
        for (int j = 0; j < 8; ++j) {
            int col = bn + wn * 64 + j * 8 + (lane & 3) * 2;
            *(float2*)(C + (size_t)r0 * MC + col)       = make_float2(acc[mi][j][0], acc[mi][j][1]);
            *(float2*)(C + (size_t)(r0 + 8) * MC + col) = make_float2(acc[mi][j][2], acc[mi][j][3]);
        }
    }
}

// ---------------- phase-1 row pass: warp per row ----------------
__global__ void k_row1() {
    int t = threadIdx.x, lane = t & 31, w = t >> 5;
    int row = blockIdx.x * 8 + w, z = blockIdx.y;
    const float4* S4 = (const float4*)&g_S[z][row][0];
    const float4* E4 = (const float4*)g_esq;
    float xs = g_xsq[z][row];

    float sv[32];
    float bestv = -1e30f; int besti = MC;
#pragma unroll
    for (int u = 0; u < 8; ++u) {
        float4 s4 = S4[u * 32 + lane];
        float4 e4 = E4[u * 32 + lane];
        int mb = (u * 32 + lane) * 4;
        float ss[4] = {s4.x, s4.y, s4.z, s4.w};
        float ee[4] = {e4.x, e4.y, e4.z, e4.w};
#pragma unroll
        for (int j = 0; j < 4; ++j) {
            float dist = xs + ee[j] - 2.f * ss[j];
            float val = -sqrtf(fmaxf(dist, 0.f));
            sv[u * 4 + j] = val;
            if (val > bestv) { bestv = val; besti = mb + j; }
        }
    }
#pragma unroll
    for (int o = 16; o; o >>= 1) {
        float ov = __shfl_xor_sync(0xFFFFFFFFu, bestv, o);
        int   oi = __shfl_xor_sync(0xFFFFFFFFu, besti, o);
        if (ov > bestv || (ov == bestv && oi < besti)) { bestv = ov; besti = oi; }
    }
    float es = 0.f;
#pragma unroll
    for (int i = 0; i < 32; i++) { sv[i] = __expf(sv[i] - bestv); es += sv[i]; }
#pragma unroll
    for (int o = 16; o; o >>= 1) es += __shfl_xor_sync(0xFFFFFFFFu, es, o);
    float invZ = 1.f / es;
    float ent = 0.f;
#pragma unroll
    for (int i = 0; i < 32; i++) { float p = sv[i] * invZ; ent += p * __logf(p + 1e-5f); }
#pragma unroll
    for (int o = 16; o; o >>= 1) ent += __shfl_xor_sync(0xFFFFFFFFu, ent, o);
    if (lane == 0) {
        g_adj[z][row] = 1.f - (-ent) * (1.f / LOGM);
        g_idx[z][row] = besti;
    }
}

// ---------------- EMA scatter ----------------
__global__ void k_scatter(const float* __restrict__ a, const float* __restrict__ v) {
    int row = blockIdx.x, t = threadIdx.x;
    int   ai = g_idx[0][row], vi = g_idx[1][row];
    float aadj = g_adj[0][row], vadj = g_adj[1][row];
    float tv = a[(size_t)row * DK + t] + v[(size_t)row * DK + t];
    atomicAdd(&g_wsum[0][vi][t], vadj * tv);
    atomicAdd(&g_wsum[1][ai][t], aadj * tv);
    if (t == 0) {
        atomicAdd(&g_cnt[0][vi], vadj);
        atomicAdd(&g_cnt[1][ai], aadj);
    }
}

// ---------------- sequential EMA count normalization ----------------
__global__ void k_ec(const float* __restrict__ ema_count) {
    __shared__ float sb[MC];
    int t = threadIdx.x;
    float ec = DECAYC * ema_count[t] + (1.f - DECAYC) * g_cnt[0][t];
    sb[t] = ec; __syncthreads();
    for (int o = 512; o > 0; o >>= 1) { if (t < o) sb[t] += sb[t + o]; __syncthreads(); }
    float n1 = sb[0]; __syncthreads();
    ec = (ec + EPSC) / (n1 + MC * EPSC) * n1;
    ec = DECAYC * ec + (1.f - DECAYC) * g_cnt[1][t];
    sb[t] = ec; __syncthreads();
    for (int o = 512; o > 0; o >>= 1) { if (t < o) sb[t] += sb[t + o]; __syncthreads(); }
    float n2 = sb[0]; __syncthreads();
    g_ec[t] = (ec + EPSC) / (n2 + MC * EPSC) * n2;
}

// ---------------- normalized new codebook ----------------
__global__ void k_en(const float* __restrict__ ema_weight) {
    __shared__ float sb[256];
    int m = blockIdx.x, t = threadIdx.x;
    float ew = (DECAYC * DECAYC) * ema_weight[(size_t)m * DK + t]
             + DECAYC * 0.5f * (1.f - DECAYC) * g_wsum[0][m][t]
             + 0.5f * (1.f - DECAYC) * g_wsum[1][m][t];
    float emb = ew / g_ec[m];
    sb[t] = emb * emb; __syncthreads();
    for (int o = 128; o > 0; o >>= 1) { if (t < o) sb[t] += sb[t + o]; __syncthreads(); }
    float nrm = sqrtf(sb[0]);
    g_en[m][t] = emb / fmaxf(nrm, 1e-8f);
}

// ---------------- phase-2 row pass: warp per row ----------------
__global__ void k_row2() {
    int t = threadIdx.x, lane = t & 31, w = t >> 5;
    int row = blockIdx.x * 8 + w, z = blockIdx.y;
    const float4* S4 = (const float4*)&g_S[z][row][0];
    float xs = g_xsq[z][row];
    float scale = 1.f / (fmaxf(sqrtf(xs), 1e-8f) * TEMPC);
    int self  = g_idx[z][row];
    int cross = g_idx[1 - z][row];

    float l[32];
    float mx = -1e30f, ps = 0.f, pc = 0.f;
#pragma unroll
    for (int u = 0; u < 8; ++u) {
        float4 s4 = S4[u * 32 + lane];
        int mb = (u * 32 + lane) * 4;
        float vv[4] = {s4.x, s4.y, s4.z, s4.w};
#pragma unroll
        for (int j = 0; j < 4; ++j) {
            float lv = vv[j] * scale;
            l[u * 4 + j] = lv;
            mx = fmaxf(mx, lv);
            if (mb + j == self)  ps = lv;
            if (mb + j == cross) pc = lv;
        }
    }
#pragma unroll
    for (int o = 16; o; o >>= 1) mx = fmaxf(mx, __shfl_xor_sync(0xFFFFFFFFu, mx, o));
    float es = 0.f;
#pragma unroll
    for (int i = 0; i < 32; i++) es += __expf(l[i] - mx);
#pragma unroll
    for (int o = 16; o; o >>= 1) {
        es += __shfl_xor_sync(0xFFFFFFFFu, es, o);
        ps += __shfl_xor_sync(0xFFFFFFFFu, ps, o);
        pc += __shfl_xor_sync(0xFFFFFFFFu, pc, o);
    }
    if (lane == 0) {
        float lse = __logf(es) + mx;
        atomicAdd(&g_loss, lse - COMMITC * ps - (1.f - COMMITC) * pc);
    }
}

__global__ void k_final(float* __restrict__ out) {
    out[0] = COMMITC * g_loss / ((float)NTOK * (float)BV);
}

extern "C" void kernel_launch(void* const* d_in, const int* in_sizes, int n_in,
                              void* d_out, int out_size) {
    const float* audio      = (const float*)d_in[0];
    const float* video      = (const float*)d_in[1];
    const float* emb        = (const float*)d_in[2];
    const float* ema_count  = (const float*)d_in[3];
    const float* ema_weight = (const float*)d_in[4];
    float* out = (float*)d_out;

    cudaFuncSetAttribute(k_mma, cudaFuncAttributeMaxDynamicSharedMemorySize, SMEMSZ);

    k_zero<<<2048, 256>>>();
    k_prepA<<<dim3(NTOK, 2), 256>>>(audio, video);
    k_prepB<<<MC, 256>>>(emb, 0);

    dim3 gg(MC / BN, NTOK / BM, 2);
    k_mma<<<gg, 256, SMEMSZ>>>(4);                    // phase 1: hi-only, K=256
    k_row1<<<dim3(NTOK / 8, 2), 256>>>();
    k_scatter<<<NTOK, 256>>>(audio, video);
    k_ec<<<1, MC>>>(ema_count);
    k_en<<<MC, 256>>>(ema_weight);
    k_prepB<<<MC, 256>>>(emb, 1);                     // split new codebook g_en
    k_mma<<<gg, 256, SMEMSZ>>>(8);                    // phase 2: 2-term, K=512
    k_row2<<<dim3(NTOK / 8, 2), 256>>>();
    k_final<<<1, 1>>>(out);
}

// round 10
// speedup vs baseline: 5.2591x; 1.4619x over previous
#include <cuda_runtime.h>
#include <cuda_fp16.h>
#include <cstdint>

#define NTOK 16384
#define DK   256
#define MC   1024
#define BV   32
#define COMMITC 0.25f
#define DECAYC  0.99f
#define EPSC    1e-5f
#define TEMPC   0.1f
#define LOGM    6.931471805599453f   /* ln(1024) */

// ---------------- static device scratch ----------------
__device__ float g_S[2][NTOK][MC];         // dot scratch (phase 1 only)
__device__ __half g_Ah[2][NTOK][DK];       // fp16 hi of A (audio/video)
__device__ __half g_Bh[MC][DK];            // fp16 hi of B (emb, then en)
__device__ float g_xsq[2][NTOK];
__device__ float g_esq[MC];
__device__ int   g_idx[2][NTOK];
__device__ float g_adj[2][NTOK];
__device__ float g_cnt[2][MC];
__device__ float g_wsum[2][MC][DK];
__device__ float g_ec[MC];
__device__ float g_en[MC][DK];
__device__ float g_esum[2][NTOK];          // fused phase-2: per-row sum exp(logit)
__device__ float g_pick[2][2][NTOK];       // fused phase-2: [z][self/cross][row]
__device__ float g_loss;

// ---------------- PTX helpers (sm_80-family only; no arch-'a' features) ----------------
__device__ __forceinline__ uint32_t smem_u32(const void* p) {
    uint32_t a;
    asm("{ .reg .u64 t; cvta.to.shared.u64 t, %1; cvt.u32.u64 %0, t; }" : "=r"(a) : "l"(p));
    return a;
}
#define CP_ASYNC16(dst, src) \
    asm volatile("cp.async.cg.shared.global [%0], [%1], 16;" :: "r"(dst), "l"(src) : "memory")
#define CP_COMMIT() asm volatile("cp.async.commit_group;" ::: "memory")
#define CP_WAIT(n)  asm volatile("cp.async.wait_group %0;" :: "n"(n) : "memory")

__device__ __forceinline__ void ldsm_x4(uint32_t* r, uint32_t addr) {
    asm volatile("ldmatrix.sync.aligned.m8n8.x4.shared.b16 {%0,%1,%2,%3}, [%4];"
        : "=r"(r[0]), "=r"(r[1]), "=r"(r[2]), "=r"(r[3]) : "r"(addr));
}
__device__ __forceinline__ void mma16816(float* d, const uint32_t* a,
                                         uint32_t b0, uint32_t b1) {
    asm volatile("mma.sync.aligned.m16n8k16.row.col.f32.f16.f16.f32 "
        "{%0,%1,%2,%3}, {%4,%5,%6,%7}, {%8,%9}, {%0,%1,%2,%3};"
        : "+f"(d[0]), "+f"(d[1]), "+f"(d[2]), "+f"(d[3])
        : "r"(a[0]), "r"(a[1]), "r"(a[2]), "r"(a[3]), "r"(b0), "r"(b1));
}

// ---------------- zero accumulators ----------------
__global__ void k_zero() {
    unsigned i = blockIdx.x * blockDim.x + threadIdx.x;
    if (i < 2u * MC * DK) ((float*)g_wsum)[i] = 0.f;
    if (i < 2u * MC)      ((float*)g_cnt)[i]  = 0.f;
    if (i < 2u * NTOK)    ((float*)g_esum)[i] = 0.f;
    if (i == 0)           g_loss = 0.f;
}

// ---------------- prep A: fp16 hi + row squared norm ----------------
__global__ void k_prepA(const float* __restrict__ a, const float* __restrict__ v) {
    int row = blockIdx.x, z = blockIdx.y, t = threadIdx.x;
    int lane = t & 31, w = t >> 5;
    const float* src = (z ? v : a) + (size_t)row * DK;
    float x = src[t];
    g_Ah[z][row][t] = __float2half(x);
    __shared__ float sp[8];
    float s = x * x;
#pragma unroll
    for (int o = 16; o; o >>= 1) s += __shfl_xor_sync(0xFFFFFFFFu, s, o);
    if (lane == 0) sp[w] = s;
    __syncthreads();
    if (t == 0) {
        float acc = 0.f;
#pragma unroll
        for (int i = 0; i < 8; i++) acc += sp[i];
        g_xsq[z][row] = acc;
    }
}

// ---------------- prep B: fp16 hi (+esq for phase 1) ----------------
__global__ void k_prepB(const float* __restrict__ embParam, int use_en) {
    int m = blockIdx.x, t = threadIdx.x;
    int lane = t & 31, w = t >> 5;
    const float* src = use_en ? &g_en[0][0] : embParam;
    float x = src[(size_t)m * DK + t];
    g_Bh[m][t] = __float2half(x);
    if (!use_en) {
        __shared__ float sp[8];
        float s = x * x;
#pragma unroll
        for (int o = 16; o; o >>= 1) s += __shfl_xor_sync(0xFFFFFFFFu, s, o);
        if (lane == 0) sp[w] = s;
        __syncthreads();
        if (t == 0) {
            float acc = 0.f;
#pragma unroll
            for (int i = 0; i < 8; i++) acc += sp[i];
            g_esq[m] = acc;
        }
    }
}

// ---------------- shared HMMA mainloop (CTA 128x128, K=256, 4 chunks of 64) ----------------
#define BM 128
#define BN 128
#define BK 64
#define NCH 4
#define STAGE (BM * BK * 2 + BN * BK * 2)  /* 32768 */
#define NSTAGE 3
#define SMEMSZ (NSTAGE * STAGE)            /* 98304 */

// Computes acc[2][8][4] for warp tile 32x64. No trailing sync in loop
// (NSTAGE=3 guarantees the prefetch target stage has been fully consumed).
#define MMA_MAINLOOP(Ag, Bg)                                                     \
    auto load_stage = [&](int s, int c) {                                        \
        uint32_t ab = sb + s * STAGE;                                            \
        uint32_t bb = ab + BM * BK * 2;                                          \
        _Pragma("unroll")                                                        \
        for (int j = 0; j < 4; ++j) {                                            \
            int idx = t + j * 256, row = idx >> 3, blk = idx & 7;                \
            CP_ASYNC16(ab + row * 128 + 16 * (blk ^ (row & 7)),                  \
                       (Ag) + (size_t)row * DK + c * BK + blk * 8);              \
        }                                                                        \
        _Pragma("unroll")                                                        \
        for (int j = 0; j < 4; ++j) {                                            \
            int idx = t + j * 256, row = idx >> 3, blk = idx & 7;                \
            CP_ASYNC16(bb + row * 128 + 16 * (blk ^ (row & 7)),                  \
                       (Bg) + (size_t)row * DK + c * BK + blk * 8);              \
        }                                                                        \
        CP_COMMIT();                                                             \
    };                                                                           \
    load_stage(0, 0);                                                            \
    load_stage(1, 1);                                                            \
    const int wm = w >> 1, wn = w & 1;                                           \
    const uint32_t swz = (uint32_t)(lane & 7) << 4;                              \
    const uint32_t kh  = (uint32_t)(lane & 16);                                  \
    const uint32_t rA  = wm * 32 + (lane & 15);                                  \
    const uint32_t rB  = wn * 64 + (lane & 15);                                  \
    _Pragma("unroll 1")                                                          \
    for (int c = 0; c < NCH; ++c) {                                              \
        if (c == NCH - 1) { CP_WAIT(0); } else { CP_WAIT(1); }                   \
        __syncthreads();                                                         \
        if (c + 2 < NCH) load_stage((c + 2) % NSTAGE, c + 2);                    \
        uint32_t ab = sb + (c % NSTAGE) * STAGE;                                 \
        uint32_t bb = ab + BM * BK * 2;                                          \
        _Pragma("unroll")                                                        \
        for (int ks = 0; ks < 4; ++ks) {                                         \
            uint32_t kx = ((uint32_t)(ks * 32) + kh) ^ swz;                      \
            uint32_t A0[4], A1[4];                                               \
            ldsm_x4(A0, ab + rA * 128 + kx);                                     \
            ldsm_x4(A1, ab + (rA + 16) * 128 + kx);                              \
            _Pragma("unroll")                                                    \
            for (int q = 0; q < 4; ++q) {                                        \
                uint32_t Bf[4];                                                  \
                ldsm_x4(Bf, bb + (rB + q * 16) * 128 + kx);                      \
                mma16816(acc[0][2 * q],     A0, Bf[0], Bf[2]);                   \
                mma16816(acc[0][2 * q + 1], A0, Bf[1], Bf[3]);                   \
                mma16816(acc[1][2 * q],     A1, Bf[0], Bf[2]);                   \
                mma16816(acc[1][2 * q + 1], A1, Bf[1], Bf[3]);                   \
            }                                                                    \
        }                                                                        \
    }

// ---------------- phase-1 GEMM: writes g_S ----------------
__global__ void __launch_bounds__(256, 2) k_mma() {
    extern __shared__ char sm[];
    const uint32_t sb = smem_u32(sm);
    const int t = threadIdx.x, lane = t & 31, w = t >> 5;
    const int z = blockIdx.z;
    const int bm = blockIdx.y * BM, bn = blockIdx.x * BN;
    const __half* Ag = &g_Ah[z][bm][0];
    const __half* Bg = &g_Bh[bn][0];

    float acc[2][8][4];
#pragma unroll
    for (int i = 0; i < 2; i++)
#pragma unroll
        for (int j = 0; j < 8; j++)
#pragma unroll
            for (int k = 0; k < 4; k++) acc[i][j][k] = 0.f;

    MMA_MAINLOOP(Ag, Bg)

    float* C = &g_S[z][0][0];
#pragma unroll
    for (int mi = 0; mi < 2; ++mi) {
        int r0 = bm + wm * 32 + mi * 16 + (lane >> 2);
#pragma unroll
        for (int j = 0; j < 8; ++j) {
            int col = bn + wn * 64 + j * 8 + (lane & 3) * 2;
            *(float2*)(C + (size_t)r0 * MC + col)       = make_float2(acc[mi][j][0], acc[mi][j][1]);
            *(float2*)(C + (size_t)(r0 + 8) * MC + col) = make_float2(acc[mi][j][2], acc[mi][j][3]);
        }
    }
}

// ---------------- phase-2 GEMM with fused InfoNCE epilogue ----------------
// logits are small (|l| < ~5) so sum-exp needs no max shift and is tile-decomposable.
__global__ void __launch_bounds__(256, 2) k_mmaL() {
    extern __shared__ char sm[];
    const uint32_t sb = smem_u32(sm);
    const int t = threadIdx.x, lane = t & 31, w = t >> 5;
    const int z = blockIdx.z;
    const int bm = blockIdx.y * BM, bn = blockIdx.x * BN;
    const __half* Ag = &g_Ah[z][bm][0];
    const __half* Bg = &g_Bh[bn][0];

    float acc[2][8][4];
#pragma unroll
    for (int i = 0; i < 2; i++)
#pragma unroll
        for (int j = 0; j < 8; j++)
#pragma unroll
            for (int k = 0; k < 4; k++) acc[i][j][k] = 0.f;

    MMA_MAINLOOP(Ag, Bg)

    const int bnw = bn + wn * 64 + (lane & 3) * 2;
#pragma unroll
    for (int mi = 0; mi < 2; ++mi) {
#pragma unroll
        for (int h = 0; h < 2; ++h) {
            int r = bm + wm * 32 + mi * 16 + h * 8 + (lane >> 2);
            float xs = g_xsq[z][r];
            float scale = 1.f / (fmaxf(sqrtf(xs), 1e-8f) * TEMPC);
            int selfI  = g_idx[z][r];
            int crossI = g_idx[1 - z][r];
            float rowsum = 0.f;
#pragma unroll
            for (int j = 0; j < 8; ++j) {
                int col = bnw + j * 8;
                float l0 = acc[mi][j][2 * h]     * scale;
                float l1 = acc[mi][j][2 * h + 1] * scale;
                rowsum += __expf(l0) + __expf(l1);
                if (col == selfI)      g_pick[z][0][r] = l0;
                if (col + 1 == selfI)  g_pick[z][0][r] = l1;
                if (col == crossI)     g_pick[z][1][r] = l0;
                if (col + 1 == crossI) g_pick[z][1][r] = l1;
            }
            rowsum += __shfl_xor_sync(0xFFFFFFFFu, rowsum, 1);
            rowsum += __shfl_xor_sync(0xFFFFFFFFu, rowsum, 2);
            if ((lane & 3) == 0) atomicAdd(&g_esum[z][r], rowsum);
        }
    }
}

// ---------------- phase-1 row pass: warp per row ----------------
__global__ void k_row1() {
    int t = threadIdx.x, lane = t & 31, w = t >> 5;
    int row = blockIdx.x * 8 + w, z = blockIdx.y;
    const float4* S4 = (const float4*)&g_S[z][row][0];
    const float4* E4 = (const float4*)g_esq;
    float xs = g_xsq[z][row];

    float sv[32];
    float bestv = -1e30f; int besti = MC;
#pragma unroll
    for (int u = 0; u < 8; ++u) {
        float4 s4 = S4[u * 32 + lane];
        float4 e4 = E4[u * 32 + lane];
        int mb = (u * 32 + lane) * 4;
        float ss[4] = {s4.x, s4.y, s4.z, s4.w};
        float ee[4] = {e4.x, e4.y, e4.z, e4.w};
#pragma unroll
        for (int j = 0; j < 4; ++j) {
            float dist = xs + ee[j] - 2.f * ss[j];
            float val = -sqrtf(fmaxf(dist, 0.f));
            sv[u * 4 + j] = val;
            if (val > bestv) { bestv = val; besti = mb + j; }
        }
    }
#pragma unroll
    for (int o = 16; o; o >>= 1) {
        float ov = __shfl_xor_sync(0xFFFFFFFFu, bestv, o);
        int   oi = __shfl_xor_sync(0xFFFFFFFFu, besti, o);
        if (ov > bestv || (ov == bestv && oi < besti)) { bestv = ov; besti = oi; }
    }
    float es = 0.f;
#pragma unroll
    for (int i = 0; i < 32; i++) { sv[i] = __expf(sv[i] - bestv); es += sv[i]; }
#pragma unroll
    for (int o = 16; o; o >>= 1) es += __shfl_xor_sync(0xFFFFFFFFu, es, o);
    float invZ = 1.f / es;
    float ent = 0.f;
#pragma unroll
    for (int i = 0; i < 32; i++) { float p = sv[i] * invZ; ent += p * __logf(p + 1e-5f); }
#pragma unroll
    for (int o = 16; o; o >>= 1) ent += __shfl_xor_sync(0xFFFFFFFFu, ent, o);
    if (lane == 0) {
        g_adj[z][row] = 1.f - (-ent) * (1.f / LOGM);
        g_idx[z][row] = besti;
    }
}

// ---------------- EMA scatter ----------------
__global__ void k_scatter(const float* __restrict__ a, const float* __restrict__ v) {
    int row = blockIdx.x, t = threadIdx.x;
    int   ai = g_idx[0][row], vi = g_idx[1][row];
    float aadj = g_adj[0][row], vadj = g_adj[1][row];
    float tv = a[(size_t)row * DK + t] + v[(size_t)row * DK + t];
    atomicAdd(&g_wsum[0][vi][t], vadj * tv);
    atomicAdd(&g_wsum[1][ai][t], aadj * tv);
    if (t == 0) {
        atomicAdd(&g_cnt[0][vi], vadj);
        atomicAdd(&g_cnt[1][ai], aadj);
    }
}

// ---------------- sequential EMA count normalization ----------------
__global__ void k_ec(const float* __restrict__ ema_count) {
    __shared__ float sb[MC];
    int t = threadIdx.x;
    float ec = DECAYC * ema_count[t] + (1.f - DECAYC) * g_cnt[0][t];
    sb[t] = ec; __syncthreads();
    for (int o = 512; o > 0; o >>= 1) { if (t < o) sb[t] += sb[t + o]; __syncthreads(); }
    float n1 = sb[0]; __syncthreads();
    ec = (ec + EPSC) / (n1 + MC * EPSC) * n1;
    ec = DECAYC * ec + (1.f - DECAYC) * g_cnt[1][t];
    sb[t] = ec; __syncthreads();
    for (int o = 512; o > 0; o >>= 1) { if (t < o) sb[t] += sb[t + o]; __syncthreads(); }
    float n2 = sb[0]; __syncthreads();
    g_ec[t] = (ec + EPSC) / (n2 + MC * EPSC) * n2;
}

// ---------------- normalized new codebook ----------------
__global__ void k_en(const float* __restrict__ ema_weight) {
    __shared__ float sb[256];
    int m = blockIdx.x, t = threadIdx.x;
    float ew = (DECAYC * DECAYC) * ema_weight[(size_t)m * DK + t]
             + DECAYC * 0.5f * (1.f - DECAYC) * g_wsum[0][m][t]
             + 0.5f * (1.f - DECAYC) * g_wsum[1][m][t];
    float emb = ew / g_ec[m];
    sb[t] = emb * emb; __syncthreads();
    for (int o = 128; o > 0; o >>= 1) { if (t < o) sb[t] += sb[t + o]; __syncthreads(); }
    float nrm = sqrtf(sb[0]);
    g_en[m][t] = emb / fmaxf(nrm, 1e-8f);
}

// ---------------- combine per-row partials into loss ----------------
__global__ void k_loss() {
    __shared__ float sp[8];
    int t = threadIdx.x, lane = t & 31, w = t >> 5;
    int row = blockIdx.x * 256 + t, z = blockIdx.y;
    float c = __logf(g_esum[z][row])
            - COMMITC * g_pick[z][0][row]
            - (1.f - COMMITC) * g_pick[z][1][row];
#pragma unroll
    for (int o = 16; o; o >>= 1) c += __shfl_xor_sync(0xFFFFFFFFu, c, o);
    if (lane == 0) sp[w] = c;
    __syncthreads();
    if (t == 0) {
        float acc = 0.f;
#pragma unroll
        for (int i = 0; i < 8; i++) acc += sp[i];
        atomicAdd(&g_loss, acc);
    }
}

__global__ void k_final(float* __restrict__ out) {
    out[0] = COMMITC * g_loss / ((float)NTOK * (float)BV);
}

extern "C" void kernel_launch(void* const* d_in, const int* in_sizes, int n_in,
                              void* d_out, int out_size) {
    const float* audio      = (const float*)d_in[0];
    const float* video      = (const float*)d_in[1];
    const float* emb        = (const float*)d_in[2];
    const float* ema_count  = (const float*)d_in[3];
    const float* ema_weight = (const float*)d_in[4];
    float* out = (float*)d_out;

    cudaFuncSetAttribute(k_mma,  cudaFuncAttributeMaxDynamicSharedMemorySize, SMEMSZ);
    cudaFuncSetAttribute(k_mmaL, cudaFuncAttributeMaxDynamicSharedMemorySize, SMEMSZ);

    k_zero<<<2048, 256>>>();
    k_prepA<<<dim3(NTOK, 2), 256>>>(audio, video);
    k_prepB<<<MC, 256>>>(emb, 0);

    dim3 gg(MC / BN, NTOK / BM, 2);
    k_mma<<<gg, 256, SMEMSZ>>>();                     // phase 1: dist dots (K=256)
    k_row1<<<dim3(NTOK / 8, 2), 256>>>();
    k_scatter<<<NTOK, 256>>>(audio, video);
    k_ec<<<1, MC>>>(ema_count);
    k_en<<<MC, 256>>>(ema_weight);
    k_prepB<<<MC, 256>>>(emb, 1);                     // fp16 new codebook g_en
    k_mmaL<<<gg, 256, SMEMSZ>>>();                    // phase 2: fused logits+softmax partials
    k_loss<<<dim3(NTOK / 256, 2), 256>>>();
    k_final<<<1, 1>>>(out);
}

// round 11
// speedup vs baseline: 6.2345x; 1.1855x over previous
#include <cuda_runtime.h>
#include <cuda_fp16.h>
#include <cstdint>

#define NTOK 16384
#define DK   256
#define MC   1024
#define BV   32
#define COMMITC 0.25f
#define DECAYC  0.99f
#define EPSC    1e-5f
#define TEMPC   0.1f
#define LOGM    6.931471805599453f   /* ln(1024) */
#define EPSM    (EPSC * (float)MC)             /* 0.01024 */
#define C2T     (0.5f * EPSC * EPSC)           /* 5e-11 */
#define C3T     (EPSC * EPSC * EPSC / 3.0f)    /* 3.333e-16 */

// ---------------- static device scratch ----------------
__device__ __half g_Ah[2][NTOK][DK];       // fp16 hi of A (audio/video)
__device__ __half g_Bh[MC][DK];            // fp16 hi of B (emb, then en)
__device__ float g_xsq[2][NTOK];
__device__ float g_esq[MC];
__device__ int   g_idx[2][NTOK];
__device__ float g_adj[2][NTOK];
__device__ float g_cnt[2][MC];
__device__ float g_wsum[2][MC][DK];
__device__ float g_ec[MC];
__device__ float g_en[MC][DK];
// fused phase-1 per-row partials
__device__ float g_Zp[2][NTOK];
__device__ float g_Ws[2][NTOK];
__device__ float g_U1[2][NTOK];
__device__ float g_U2[2][NTOK];
__device__ unsigned long long g_key[2][NTOK];
// fused phase-2 per-row partials
__device__ float g_esum[2][NTOK];
__device__ float g_pick[2][2][NTOK];
__device__ float g_loss;

// ---------------- PTX helpers (sm_80-family only; no arch-'a' features) ----------------
__device__ __forceinline__ uint32_t smem_u32(const void* p) {
    uint32_t a;
    asm("{ .reg .u64 t; cvta.to.shared.u64 t, %1; cvt.u32.u64 %0, t; }" : "=r"(a) : "l"(p));
    return a;
}
#define CP_ASYNC16(dst, src) \
    asm volatile("cp.async.cg.shared.global [%0], [%1], 16;" :: "r"(dst), "l"(src) : "memory")
#define CP_COMMIT() asm volatile("cp.async.commit_group;" ::: "memory")
#define CP_WAIT(n)  asm volatile("cp.async.wait_group %0;" :: "n"(n) : "memory")

__device__ __forceinline__ void ldsm_x4(uint32_t* r, uint32_t addr) {
    asm volatile("ldmatrix.sync.aligned.m8n8.x4.shared.b16 {%0,%1,%2,%3}, [%4];"
        : "=r"(r[0]), "=r"(r[1]), "=r"(r[2]), "=r"(r[3]) : "r"(addr));
}
__device__ __forceinline__ void mma16816(float* d, const uint32_t* a,
                                         uint32_t b0, uint32_t b1) {
    asm volatile("mma.sync.aligned.m16n8k16.row.col.f32.f16.f16.f32 "
        "{%0,%1,%2,%3}, {%4,%5,%6,%7}, {%8,%9}, {%0,%1,%2,%3};"
        : "+f"(d[0]), "+f"(d[1]), "+f"(d[2]), "+f"(d[3])
        : "r"(a[0]), "r"(a[1]), "r"(a[2]), "r"(a[3]), "r"(b0), "r"(b1));
}

// degree-4 poly exp for |t| <= ~0.04 (abs err < 2e-10)
__device__ __forceinline__ float expp(float t) {
    float e = fmaf(t, 0.041666668f, 0.16666667f);
    e = fmaf(t, e, 0.5f);
    e = fmaf(t, e, 1.0f);
    e = fmaf(t, e, 1.0f);
    return e;
}
// orderable encoding of float (monotone increasing map to uint32)
__device__ __forceinline__ uint32_t fenc(float f) {
    uint32_t u = __float_as_uint(f);
    return u ^ ((u & 0x80000000u) ? 0xFFFFFFFFu : 0x80000000u);
}

// ---------------- zero accumulators ----------------
__global__ void k_zero() {
    unsigned i = blockIdx.x * blockDim.x + threadIdx.x;
    if (i < 2u * MC * DK) ((float*)g_wsum)[i] = 0.f;
    if (i < 2u * MC)      ((float*)g_cnt)[i]  = 0.f;
    if (i < 2u * NTOK) {
        ((float*)g_esum)[i] = 0.f;
        ((float*)g_Zp)[i] = 0.f;
        ((float*)g_Ws)[i] = 0.f;
        ((float*)g_U1)[i] = 0.f;
        ((float*)g_U2)[i] = 0.f;
        ((unsigned long long*)g_key)[i] = 0ull;
    }
    if (i == 0) g_loss = 0.f;
}

// ---------------- prep A: fp16 hi + row squared norm ----------------
__global__ void k_prepA(const float* __restrict__ a, const float* __restrict__ v) {
    int row = blockIdx.x, z = blockIdx.y, t = threadIdx.x;
    int lane = t & 31, w = t >> 5;
    const float* src = (z ? v : a) + (size_t)row * DK;
    float x = src[t];
    g_Ah[z][row][t] = __float2half(x);
    __shared__ float sp[8];
    float s = x * x;
#pragma unroll
    for (int o = 16; o; o >>= 1) s += __shfl_xor_sync(0xFFFFFFFFu, s, o);
    if (lane == 0) sp[w] = s;
    __syncthreads();
    if (t == 0) {
        float acc = 0.f;
#pragma unroll
        for (int i = 0; i < 8; i++) acc += sp[i];
        g_xsq[z][row] = acc;
    }
}

// ---------------- prep B: fp16 hi (+esq for phase 1) ----------------
__global__ void k_prepB(const float* __restrict__ embParam, int use_en) {
    int m = blockIdx.x, t = threadIdx.x;
    int lane = t & 31, w = t >> 5;
    const float* src = use_en ? &g_en[0][0] : embParam;
    float x = src[(size_t)m * DK + t];
    g_Bh[m][t] = __float2half(x);
    if (!use_en) {
        __shared__ float sp[8];
        float s = x * x;
#pragma unroll
        for (int o = 16; o; o >>= 1) s += __shfl_xor_sync(0xFFFFFFFFu, s, o);
        if (lane == 0) sp[w] = s;
        __syncthreads();
        if (t == 0) {
            float acc = 0.f;
#pragma unroll
            for (int i = 0; i < 8; i++) acc += sp[i];
            g_esq[m] = acc;
        }
    }
}

// ---------------- shared HMMA mainloop (CTA 128x128, K=256, 4 chunks of 64) ----------------
#define BM 128
#define BN 128
#define BK 64
#define NCH 4
#define STAGE (BM * BK * 2 + BN * BK * 2)  /* 32768 */
#define NSTAGE 3
#define SMEMSZ (NSTAGE * STAGE)            /* 98304 */

#define MMA_MAINLOOP(Ag, Bg)                                                     \
    auto load_stage = [&](int s, int c) {                                        \
        uint32_t ab = sb + s * STAGE;                                            \
        uint32_t bb = ab + BM * BK * 2;                                          \
        _Pragma("unroll")                                                        \
        for (int j = 0; j < 4; ++j) {                                            \
            int idx = t + j * 256, row = idx >> 3, blk = idx & 7;                \
            CP_ASYNC16(ab + row * 128 + 16 * (blk ^ (row & 7)),                  \
                       (Ag) + (size_t)row * DK + c * BK + blk * 8);              \
        }                                                                        \
        _Pragma("unroll")                                                        \
        for (int j = 0; j < 4; ++j) {                                            \
            int idx = t + j * 256, row = idx >> 3, blk = idx & 7;                \
            CP_ASYNC16(bb + row * 128 + 16 * (blk ^ (row & 7)),                  \
                       (Bg) + (size_t)row * DK + c * BK + blk * 8);              \
        }                                                                        \
        CP_COMMIT();                                                             \
    };                                                                           \
    load_stage(0, 0);                                                            \
    load_stage(1, 1);                                                            \
    const int wm = w >> 1, wn = w & 1;                                           \
    const uint32_t swz = (uint32_t)(lane & 7) << 4;                              \
    const uint32_t kh  = (uint32_t)(lane & 16);                                  \
    const uint32_t rA  = wm * 32 + (lane & 15);                                  \
    const uint32_t rB  = wn * 64 + (lane & 15);                                  \
    _Pragma("unroll 1")                                                          \
    for (int c = 0; c < NCH; ++c) {                                              \
        if (c == NCH - 1) { CP_WAIT(0); } else { CP_WAIT(1); }                   \
        __syncthreads();                                                         \
        if (c + 2 < NCH) load_stage((c + 2) % NSTAGE, c + 2);                    \
        uint32_t ab = sb + (c % NSTAGE) * STAGE;                                 \
        uint32_t bb = ab + BM * BK * 2;                                          \
        _Pragma("unroll")                                                        \
        for (int ks = 0; ks < 4; ++ks) {                                         \
            uint32_t kx = ((uint32_t)(ks * 32) + kh) ^ swz;                      \
            uint32_t A0[4], A1[4];                                               \
            ldsm_x4(A0, ab + rA * 128 + kx);                                     \
            ldsm_x4(A1, ab + (rA + 16) * 128 + kx);                              \
            _Pragma("unroll")                                                    \
            for (int q = 0; q < 4; ++q) {                                        \
                uint32_t Bf[4];                                                  \
                ldsm_x4(Bf, bb + (rB + q * 16) * 128 + kx);                      \
                mma16816(acc[0][2 * q],     A0, Bf[0], Bf[2]);                   \
                mma16816(acc[0][2 * q + 1], A0, Bf[1], Bf[3]);                   \
                mma16816(acc[1][2 * q],     A1, Bf[0], Bf[2]);                   \
                mma16816(acc[1][2 * q + 1], A1, Bf[1], Bf[3]);                   \
            }                                                                    \
        }                                                                        \
    }

// ---------------- phase-1 GEMM with fused dist/softmax-partials epilogue ----------------
// s' = sqrt(xs) - sqrt(dist), |s'| <= max||e|| ~ 0.033 -> poly exp, no max pass.
__global__ void __launch_bounds__(256, 2) k_mmaD() {
    extern __shared__ char sm[];
    const uint32_t sb = smem_u32(sm);
    const int t = threadIdx.x, lane = t & 31, w = t >> 5;
    const int z = blockIdx.z;
    const int bm = blockIdx.y * BM, bn = blockIdx.x * BN;
    const __half* Ag = &g_Ah[z][bm][0];
    const __half* Bg = &g_Bh[bn][0];

    float acc[2][8][4];
#pragma unroll
    for (int i = 0; i < 2; i++)
#pragma unroll
        for (int j = 0; j < 8; j++)
#pragma unroll
            for (int k = 0; k < 4; k++) acc[i][j][k] = 0.f;

    MMA_MAINLOOP(Ag, Bg)

    const int bnw = bn + wn * 64 + (lane & 3) * 2;
#pragma unroll
    for (int mi = 0; mi < 2; ++mi) {
#pragma unroll
        for (int h = 0; h < 2; ++h) {
            int r = bm + wm * 32 + mi * 16 + h * 8 + (lane >> 2);
            float xs = g_xsq[z][r];
            float sq = sqrtf(xs);
            float zp = 0.f, ws = 0.f, u1 = 0.f, u2 = 0.f;
            float bs = -1e30f; int bidx = 0;
#pragma unroll
            for (int j = 0; j < 8; ++j) {
                int col = bnw + j * 8;
#pragma unroll
                for (int e = 0; e < 2; ++e) {
                    float S = acc[mi][j][2 * h + e];
                    float dist = fmaxf(fmaf(-2.f, S, xs + g_esq[col + e]), 0.f);
                    float sp = sq - sqrtf(dist);
                    float rr = expp(sp);
                    float uu = expp(-sp);
                    zp += rr;
                    ws = fmaf(sp, rr, ws);
                    u1 += uu;
                    u2 = fmaf(uu, uu, u2);
                    if (sp > bs) { bs = sp; bidx = col + e; }
                }
            }
            // pack argmax key: larger s' wins; tie -> smaller index wins
            unsigned long long key =
                ((unsigned long long)fenc(bs) << 32) | (uint32_t)(MC - 1 - bidx);
#pragma unroll
            for (int o = 1; o <= 2; o <<= 1) {
                zp += __shfl_xor_sync(0xFFFFFFFFu, zp, o);
                ws += __shfl_xor_sync(0xFFFFFFFFu, ws, o);
                u1 += __shfl_xor_sync(0xFFFFFFFFu, u1, o);
                u2 += __shfl_xor_sync(0xFFFFFFFFu, u2, o);
                unsigned long long ok = __shfl_xor_sync(0xFFFFFFFFu, key, o);
                if (ok > key) key = ok;
            }
            if ((lane & 3) == 0) {
                atomicAdd(&g_Zp[z][r], zp);
                atomicAdd(&g_Ws[z][r], ws);
                atomicAdd(&g_U1[z][r], u1);
                atomicAdd(&g_U2[z][r], u2);
                atomicMax(&g_key[z][r], key);
            }
        }
    }
}

// ---------------- combine phase-1 partials: adj + idx per row ----------------
// logM - H = -log(Z/M) + W/Z + M*eps - (eps^2/2) Z*U1 + (eps^3/3) Z^2*U2
__global__ void k_row1f() {
    int row = blockIdx.x * 256 + threadIdx.x, z = blockIdx.y;
    float Z = g_Zp[z][row];
    float D = EPSM + g_Ws[z][row] / Z - __logf(Z * (1.0f / MC))
            - C2T * Z * g_U1[z][row]
            + C3T * Z * Z * g_U2[z][row];
    g_adj[z][row] = D * (1.0f / LOGM);
    g_idx[z][row] = MC - 1 - (int)(g_key[z][row] & 0xFFFFFFFFull);
}

// ---------------- phase-2 GEMM with fused InfoNCE epilogue ----------------
__global__ void __launch_bounds__(256, 2) k_mmaL() {
    extern __shared__ char sm[];
    const uint32_t sb = smem_u32(sm);
    const int t = threadIdx.x, lane = t & 31, w = t >> 5;
    const int z = blockIdx.z;
    const int bm = blockIdx.y * BM, bn = blockIdx.x * BN;
    const __half* Ag = &g_Ah[z][bm][0];
    const __half* Bg = &g_Bh[bn][0];

    float acc[2][8][4];
#pragma unroll
    for (int i = 0; i < 2; i++)
#pragma unroll
        for (int j = 0; j < 8; j++)
#pragma unroll
            for (int k = 0; k < 4; k++) acc[i][j][k] = 0.f;

    MMA_MAINLOOP(Ag, Bg)

    const int bnw = bn + wn * 64 + (lane & 3) * 2;
#pragma unroll
    for (int mi = 0; mi < 2; ++mi) {
#pragma unroll
        for (int h = 0; h < 2; ++h) {
            int r = bm + wm * 32 + mi * 16 + h * 8 + (lane >> 2);
            float xs = g_xsq[z][r];
            float scale = 1.f / (fmaxf(sqrtf(xs), 1e-8f) * TEMPC);
            int selfI  = g_idx[z][r];
            int crossI = g_idx[1 - z][r];
            float rowsum = 0.f;
#pragma unroll
            for (int j = 0; j < 8; ++j) {
                int col = bnw + j * 8;
                float l0 = acc[mi][j][2 * h]     * scale;
                float l1 = acc[mi][j][2 * h + 1] * scale;
                rowsum += __expf(l0) + __expf(l1);
                if (col == selfI)      g_pick[z][0][r] = l0;
                if (col + 1 == selfI)  g_pick[z][0][r] = l1;
                if (col == crossI)     g_pick[z][1][r] = l0;
                if (col + 1 == crossI) g_pick[z][1][r] = l1;
            }
            rowsum += __shfl_xor_sync(0xFFFFFFFFu, rowsum, 1);
            rowsum += __shfl_xor_sync(0xFFFFFFFFu, rowsum, 2);
            if ((lane & 3) == 0) atomicAdd(&g_esum[z][r], rowsum);
        }
    }
}

// ---------------- EMA scatter ----------------
__global__ void k_scatter(const float* __restrict__ a, const float* __restrict__ v) {
    int row = blockIdx.x, t = threadIdx.x;
    int   ai = g_idx[0][row], vi = g_idx[1][row];
    float aadj = g_adj[0][row], vadj = g_adj[1][row];
    float tv = a[(size_t)row * DK + t] + v[(size_t)row * DK + t];
    atomicAdd(&g_wsum[0][vi][t], vadj * tv);
    atomicAdd(&g_wsum[1][ai][t], aadj * tv);
    if (t == 0) {
        atomicAdd(&g_cnt[0][vi], vadj);
        atomicAdd(&g_cnt[1][ai], aadj);
    }
}

// ---------------- sequential EMA count normalization ----------------
__global__ void k_ec(const float* __restrict__ ema_count) {
    __shared__ float sb[MC];
    int t = threadIdx.x;
    float ec = DECAYC * ema_count[t] + (1.f - DECAYC) * g_cnt[0][t];
    sb[t] = ec; __syncthreads();
    for (int o = 512; o > 0; o >>= 1) { if (t < o) sb[t] += sb[t + o]; __syncthreads(); }
    float n1 = sb[0]; __syncthreads();
    ec = (ec + EPSC) / (n1 + MC * EPSC) * n1;
    ec = DECAYC * ec + (1.f - DECAYC) * g_cnt[1][t];
    sb[t] = ec; __syncthreads();
    for (int o = 512; o > 0; o >>= 1) { if (t < o) sb[t] += sb[t + o]; __syncthreads(); }
    float n2 = sb[0]; __syncthreads();
    g_ec[t] = (ec + EPSC) / (n2 + MC * EPSC) * n2;
}

// ---------------- normalized new codebook ----------------
__global__ void k_en(const float* __restrict__ ema_weight) {
    __shared__ float sb[256];
    int m = blockIdx.x, t = threadIdx.x;
    float ew = (DECAYC * DECAYC) * ema_weight[(size_t)m * DK + t]
             + DECAYC * 0.5f * (1.f - DECAYC) * g_wsum[0][m][t]
             + 0.5f * (1.f - DECAYC) * g_wsum[1][m][t];
    float emb = ew / g_ec[m];
    sb[t] = emb * emb; __syncthreads();
    for (int o = 128; o > 0; o >>= 1) { if (t < o) sb[t] += sb[t + o]; __syncthreads(); }
    float nrm = sqrtf(sb[0]);
    g_en[m][t] = emb / fmaxf(nrm, 1e-8f);
}

// ---------------- combine per-row partials into loss ----------------
__global__ void k_loss() {
    __shared__ float sp[8];
    int t = threadIdx.x, lane = t & 31, w = t >> 5;
    int row = blockIdx.x * 256 + t, z = blockIdx.y;
    float c = __logf(g_esum[z][row])
            - COMMITC * g_pick[z][0][row]
            - (1.f - COMMITC) * g_pick[z][1][row];
#pragma unroll
    for (int o = 16; o; o >>= 1) c += __shfl_xor_sync(0xFFFFFFFFu, c, o);
    if (lane == 0) sp[w] = c;
    __syncthreads();
    if (t == 0) {
        float acc = 0.f;
#pragma unroll
        for (int i = 0; i < 8; i++) acc += sp[i];
        atomicAdd(&g_loss, acc);
    }
}

__global__ void k_final(float* __restrict__ out) {
    out[0] = COMMITC * g_loss / ((float)NTOK * (float)BV);
}

extern "C" void kernel_launch(void* const* d_in, const int* in_sizes, int n_in,
                              void* d_out, int out_size) {
    const float* audio      = (const float*)d_in[0];
    const float* video      = (const float*)d_in[1];
    const float* emb        = (const float*)d_in[2];
    const float* ema_count  = (const float*)d_in[3];
    const float* ema_weight = (const float*)d_in[4];
    float* out = (float*)d_out;

    cudaFuncSetAttribute(k_mmaD, cudaFuncAttributeMaxDynamicSharedMemorySize, SMEMSZ);
    cudaFuncSetAttribute(k_mmaL, cudaFuncAttributeMaxDynamicSharedMemorySize, SMEMSZ);

    k_zero<<<2048, 256>>>();
    k_prepA<<<dim3(NTOK, 2), 256>>>(audio, video);
    k_prepB<<<MC, 256>>>(emb, 0);

    dim3 gg(MC / BN, NTOK / BM, 2);
    k_mmaD<<<gg, 256, SMEMSZ>>>();                    // phase 1: fused dist partials
    k_row1f<<<dim3(NTOK / 256, 2), 256>>>();          // combine -> adj, idx
    k_scatter<<<NTOK, 256>>>(audio, video);
    k_ec<<<1, MC>>>(ema_count);
    k_en<<<MC, 256>>>(ema_weight);
    k_prepB<<<MC, 256>>>(emb, 1);                     // fp16 new codebook g_en
    k_mmaL<<<gg, 256, SMEMSZ>>>();                    // phase 2: fused logits partials
    k_loss<<<dim3(NTOK / 256, 2), 256>>>();
    k_final<<<1, 1>>>(out);
}

// round 12
// speedup vs baseline: 6.3911x; 1.0251x over previous
#include <cuda_runtime.h>
#include <cuda_fp16.h>
#include <cstdint>

#define NTOK 16384
#define DK   256
#define MC   1024
#define BV   32
#define COMMITC 0.25f
#define DECAYC  0.99f
#define EPSC    1e-5f
#define TEMPC   0.1f
#define LOGM    6.931471805599453f   /* ln(1024) */
#define EPSM    (EPSC * (float)MC)             /* 0.01024 */
#define C2T     (0.5f * EPSC * EPSC)           /* 5e-11 */

// ---------------- static device scratch ----------------
__device__ __half g_Ah[2][NTOK][DK];       // fp16 hi of A (audio/video)
__device__ __half g_Bh[MC][DK];            // fp16 hi of B (emb, then en)
__device__ float g_xsq[2][NTOK];
__device__ float g_esq[MC];
__device__ int   g_idx[2][NTOK];
__device__ float g_cnt[2][MC];
__device__ float g_wsum[2][MC][DK];
__device__ float g_ec[MC];
// fused phase-1 per-row partials: power sums of s' and packed argmax key
__device__ float g_S1[2][NTOK];
__device__ float g_S2[2][NTOK];
__device__ float g_S3[2][NTOK];
__device__ float g_S4[2][NTOK];
__device__ unsigned int g_key[2][NTOK];
// fused phase-2 per-row partials
__device__ float g_esum[2][NTOK];
__device__ float g_pick[2][2][NTOK];

// ---------------- PTX helpers (sm_80-family only; no arch-'a' features) ----------------
__device__ __forceinline__ uint32_t smem_u32(const void* p) {
    uint32_t a;
    asm("{ .reg .u64 t; cvta.to.shared.u64 t, %1; cvt.u32.u64 %0, t; }" : "=r"(a) : "l"(p));
    return a;
}
#define CP_ASYNC16(dst, src) \
    asm volatile("cp.async.cg.shared.global [%0], [%1], 16;" :: "r"(dst), "l"(src) : "memory")
#define CP_COMMIT() asm volatile("cp.async.commit_group;" ::: "memory")
#define CP_WAIT(n)  asm volatile("cp.async.wait_group %0;" :: "n"(n) : "memory")

__device__ __forceinline__ void ldsm_x4(uint32_t* r, uint32_t addr) {
    asm volatile("ldmatrix.sync.aligned.m8n8.x4.shared.b16 {%0,%1,%2,%3}, [%4];"
        : "=r"(r[0]), "=r"(r[1]), "=r"(r[2]), "=r"(r[3]) : "r"(addr));
}
__device__ __forceinline__ void mma16816(float* d, const uint32_t* a,
                                         uint32_t b0, uint32_t b1) {
    asm volatile("mma.sync.aligned.m16n8k16.row.col.f32.f16.f16.f32 "
        "{%0,%1,%2,%3}, {%4,%5,%6,%7}, {%8,%9}, {%0,%1,%2,%3};"
        : "+f"(d[0]), "+f"(d[1]), "+f"(d[2]), "+f"(d[3])
        : "r"(a[0]), "r"(a[1]), "r"(a[2]), "r"(a[3]), "r"(b0), "r"(b1));
}

// ---------------- zero accumulators (every launch, graph replay) ----------------
__global__ void k_zero(float* __restrict__ out) {
    unsigned i = blockIdx.x * blockDim.x + threadIdx.x;
    if (i < 2u * MC * DK) ((float*)g_wsum)[i] = 0.f;
    if (i < 2u * MC)      ((float*)g_cnt)[i]  = 0.f;
    if (i < 2u * NTOK) {
        ((float*)g_esum)[i] = 0.f;
        ((float*)g_S1)[i] = 0.f;
        ((float*)g_S2)[i] = 0.f;
        ((float*)g_S3)[i] = 0.f;
        ((float*)g_S4)[i] = 0.f;
        ((unsigned int*)g_key)[i] = 0u;
    }
    if (i == 0) out[0] = 0.f;
}

// ---------------- prep A: fp16 hi + row squared norm ----------------
__global__ void k_prepA(const float* __restrict__ a, const float* __restrict__ v) {
    int row = blockIdx.x, z = blockIdx.y, t = threadIdx.x;
    int lane = t & 31, w = t >> 5;
    const float* src = (z ? v : a) + (size_t)row * DK;
    float x = src[t];
    g_Ah[z][row][t] = __float2half(x);
    __shared__ float sp[8];
    float s = x * x;
#pragma unroll
    for (int o = 16; o; o >>= 1) s += __shfl_xor_sync(0xFFFFFFFFu, s, o);
    if (lane == 0) sp[w] = s;
    __syncthreads();
    if (t == 0) {
        float acc = 0.f;
#pragma unroll
        for (int i = 0; i < 8; i++) acc += sp[i];
        g_xsq[z][row] = acc;
    }
}

// ---------------- prep B (phase 1 only): fp16 hi + esq ----------------
__global__ void k_prepB(const float* __restrict__ embParam) {
    int m = blockIdx.x, t = threadIdx.x;
    int lane = t & 31, w = t >> 5;
    float x = embParam[(size_t)m * DK + t];
    g_Bh[m][t] = __float2half(x);
    __shared__ float sp[8];
    float s = x * x;
#pragma unroll
    for (int o = 16; o; o >>= 1) s += __shfl_xor_sync(0xFFFFFFFFu, s, o);
    if (lane == 0) sp[w] = s;
    __syncthreads();
    if (t == 0) {
        float acc = 0.f;
#pragma unroll
        for (int i = 0; i < 8; i++) acc += sp[i];
        g_esq[m] = acc;
    }
}

// ---------------- shared HMMA mainloop (CTA 128x128, K=256, 4 chunks of 64) ----------------
#define BM 128
#define BN 128
#define BK 64
#define NCH 4
#define STAGE (BM * BK * 2 + BN * BK * 2)  /* 32768 */
#define NSTAGE 3
#define SMEMSZ (NSTAGE * STAGE)            /* 98304 */

#define MMA_MAINLOOP(Ag, Bg)                                                     \
    auto load_stage = [&](int s, int c) {                                        \
        uint32_t ab = sb + s * STAGE;                                            \
        uint32_t bb = ab + BM * BK * 2;                                          \
        _Pragma("unroll")                                                        \
        for (int j = 0; j < 4; ++j) {                                            \
            int idx = t + j * 256, row = idx >> 3, blk = idx & 7;                \
            CP_ASYNC16(ab + row * 128 + 16 * (blk ^ (row & 7)),                  \
                       (Ag) + (size_t)row * DK + c * BK + blk * 8);              \
        }                                                                        \
        _Pragma("unroll")                                                        \
        for (int j = 0; j < 4; ++j) {                                            \
            int idx = t + j * 256, row = idx >> 3, blk = idx & 7;                \
            CP_ASYNC16(bb + row * 128 + 16 * (blk ^ (row & 7)),                  \
                       (Bg) + (size_t)row * DK + c * BK + blk * 8);              \
        }                                                                        \
        CP_COMMIT();                                                             \
    };                                                                           \
    load_stage(0, 0);                                                            \
    load_stage(1, 1);                                                            \
    const int wm = w >> 1, wn = w & 1;                                           \
    const uint32_t swz = (uint32_t)(lane & 7) << 4;                              \
    const uint32_t kh  = (uint32_t)(lane & 16);                                  \
    const uint32_t rA  = wm * 32 + (lane & 15);                                  \
    const uint32_t rB  = wn * 64 + (lane & 15);                                  \
    _Pragma("unroll 1")                                                          \
    for (int c = 0; c < NCH; ++c) {                                              \
        if (c == NCH - 1) { CP_WAIT(0); } else { CP_WAIT(1); }                   \
        __syncthreads();                                                         \
        if (c + 2 < NCH) load_stage((c + 2) % NSTAGE, c + 2);                    \
        uint32_t ab = sb + (c % NSTAGE) * STAGE;                                 \
        uint32_t bb = ab + BM * BK * 2;                                          \
        _Pragma("unroll")                                                        \
        for (int ks = 0; ks < 4; ++ks) {                                         \
            uint32_t kx = ((uint32_t)(ks * 32) + kh) ^ swz;                      \
            uint32_t A0[4], A1[4];                                               \
            ldsm_x4(A0, ab + rA * 128 + kx);                                     \
            ldsm_x4(A1, ab + (rA + 16) * 128 + kx);                              \
            _Pragma("unroll")                                                    \
            for (int q = 0; q < 4; ++q) {                                        \
                uint32_t Bf[4];                                                  \
                ldsm_x4(Bf, bb + (rB + q * 16) * 128 + kx);                      \
                mma16816(acc[0][2 * q],     A0, Bf[0], Bf[2]);                   \
                mma16816(acc[0][2 * q + 1], A0, Bf[1], Bf[3]);                   \
                mma16816(acc[1][2 * q],     A1, Bf[0], Bf[2]);                   \
                mma16816(acc[1][2 * q + 1], A1, Bf[1], Bf[3]);                   \
            }                                                                    \
        }                                                                        \
    }

// ---------------- phase-1 GEMM, epilogue accumulates power sums of s' ----------------
// s' = sqrt(xs) - sqrt(dist), |s'| <= ||e|| <= ~0.04 (Cauchy-Schwarz).
// Z/W/U1 are linear in S1..S4 (4th-order poly exp) -> only 5 ops/element here.
__global__ void __launch_bounds__(256, 2) k_mmaD() {
    extern __shared__ char sm[];
    const uint32_t sb = smem_u32(sm);
    const int t = threadIdx.x, lane = t & 31, w = t >> 5;
    const int z = blockIdx.z;
    const int bm = blockIdx.y * BM, bn = blockIdx.x * BN;
    const __half* Ag = &g_Ah[z][bm][0];
    const __half* Bg = &g_Bh[bn][0];

    float acc[2][8][4];
#pragma unroll
    for (int i = 0; i < 2; i++)
#pragma unroll
        for (int j = 0; j < 8; j++)
#pragma unroll
            for (int k = 0; k < 4; k++) acc[i][j][k] = 0.f;

    MMA_MAINLOOP(Ag, Bg)

    const int bnw = bn + wn * 64 + (lane & 3) * 2;
#pragma unroll
    for (int mi = 0; mi < 2; ++mi) {
#pragma unroll
        for (int h = 0; h < 2; ++h) {
            int r = bm + wm * 32 + mi * 16 + h * 8 + (lane >> 2);
            float xs = g_xsq[z][r];
            float sq = sqrtf(xs);
            float s1 = 0.f, s2 = 0.f, s3 = 0.f, s4 = 0.f;
            float bs = -1e30f; int bc = 0;
#pragma unroll
            for (int j = 0; j < 8; ++j) {
                int col = bnw + j * 8;
#pragma unroll
                for (int e = 0; e < 2; ++e) {
                    float S = acc[mi][j][2 * h + e];
                    float dist = fmaxf(fmaf(-2.f, S, xs + g_esq[col + e]), 0.f);
                    float sp = sq - sqrtf(dist);
                    float sp2 = sp * sp;
                    s1 += sp;
                    s2 += sp2;
                    s3 = fmaf(sp, sp2, s3);
                    s4 = fmaf(sp2, sp2, s4);
                    if (sp > bs) { bs = sp; bc = col + e; }
                }
            }
            // 32-bit argmax key: larger s' wins, tie -> smaller index.
            float bsc = fminf(fmaxf(bs, -0.06f), 0.0624f) + 1.0f;
            uint32_t key = ((__float_as_uint(bsc) - 0x3F700000u) << 10)
                         | (uint32_t)(MC - 1 - bc);
#pragma unroll
            for (int o = 1; o <= 2; o <<= 1) {
                s1 += __shfl_xor_sync(0xFFFFFFFFu, s1, o);
                s2 += __shfl_xor_sync(0xFFFFFFFFu, s2, o);
                s3 += __shfl_xor_sync(0xFFFFFFFFu, s3, o);
                s4 += __shfl_xor_sync(0xFFFFFFFFu, s4, o);
                uint32_t ok = __shfl_xor_sync(0xFFFFFFFFu, key, o);
                key = (ok > key) ? ok : key;
            }
            if ((lane & 3) == 0) {
                atomicAdd(&g_S1[z][r], s1);
                atomicAdd(&g_S2[z][r], s2);
                atomicAdd(&g_S3[z][r], s3);
                atomicAdd(&g_S4[z][r], s4);
                atomicMax(&g_key[z][r], key);
            }
        }
    }
}

// ---------------- phase-2 GEMM with fused InfoNCE epilogue ----------------
__global__ void __launch_bounds__(256, 2) k_mmaL() {
    extern __shared__ char sm[];
    const uint32_t sb = smem_u32(sm);
    const int t = threadIdx.x, lane = t & 31, w = t >> 5;
    const int z = blockIdx.z;
    const int bm = blockIdx.y * BM, bn = blockIdx.x * BN;
    const __half* Ag = &g_Ah[z][bm][0];
    const __half* Bg = &g_Bh[bn][0];

    float acc[2][8][4];
#pragma unroll
    for (int i = 0; i < 2; i++)
#pragma unroll
        for (int j = 0; j < 8; j++)
#pragma unroll
            for (int k = 0; k < 4; k++) acc[i][j][k] = 0.f;

    MMA_MAINLOOP(Ag, Bg)

    const int bnw = bn + wn * 64 + (lane & 3) * 2;
#pragma unroll
    for (int mi = 0; mi < 2; ++mi) {
#pragma unroll
        for (int h = 0; h < 2; ++h) {
            int r = bm + wm * 32 + mi * 16 + h * 8 + (lane >> 2);
            float xs = g_xsq[z][r];
            float scale = 1.f / (fmaxf(sqrtf(xs), 1e-8f) * TEMPC);
            int selfI  = g_idx[z][r];
            int crossI = g_idx[1 - z][r];
            float rowsum = 0.f;
#pragma unroll
            for (int j = 0; j < 8; ++j) {
                int col = bnw + j * 8;
                float l0 = acc[mi][j][2 * h]     * scale;
                float l1 = acc[mi][j][2 * h + 1] * scale;
                rowsum += __expf(l0) + __expf(l1);
                if (col == selfI)      g_pick[z][0][r] = l0;
                if (col + 1 == selfI)  g_pick[z][0][r] = l1;
                if (col == crossI)     g_pick[z][1][r] = l0;
                if (col + 1 == crossI) g_pick[z][1][r] = l1;
            }
            rowsum += __shfl_xor_sync(0xFFFFFFFFu, rowsum, 1);
            rowsum += __shfl_xor_sync(0xFFFFFFFFu, rowsum, 2);
            if ((lane & 3) == 0) atomicAdd(&g_esum[z][r], rowsum);
        }
    }
}

// ---------------- EMA scatter (+ per-row adj/idx combine from moments) ----------------
// logM - H = -log(Z/M) + W/Z + M*eps - (eps^2/2) Z*U1, with
// Z = M+S1+S2/2+S3/6+S4/24, W = S1+S2+S3/2+S4/6, U1 = M-S1+S2/2-S3/6+S4/24.
__global__ void k_scatter(const float* __restrict__ a, const float* __restrict__ v) {
    __shared__ float sadj[2];
    __shared__ int   sidx[2];
    int row = blockIdx.x, t = threadIdx.x;
    if (t < 2) {
        int z = t;
        float s1 = g_S1[z][row], s2 = g_S2[z][row];
        float s3 = g_S3[z][row], s4 = g_S4[z][row];
        float Z  = (float)MC + s1 + 0.5f * s2 + (1.f / 6.f) * s3 + (1.f / 24.f) * s4;
        float W  = s1 + s2 + 0.5f * s3 + (1.f / 6.f) * s4;
        float U1 = (float)MC - s1 + 0.5f * s2 - (1.f / 6.f) * s3 + (1.f / 24.f) * s4;
        float D  = EPSM + W / Z - __logf(Z * (1.0f / MC)) - C2T * Z * U1;
        sadj[z] = D * (1.0f / LOGM);
        int idx = MC - 1 - (int)(g_key[z][row] & 1023u);
        sidx[z] = idx;
        g_idx[z][row] = idx;
    }
    __syncthreads();
    int   ai = sidx[0], vi = sidx[1];
    float aadj = sadj[0], vadj = sadj[1];
    float tv = a[(size_t)row * DK + t] + v[(size_t)row * DK + t];
    atomicAdd(&g_wsum[0][vi][t], vadj * tv);
    atomicAdd(&g_wsum[1][ai][t], aadj * tv);
    if (t == 0) {
        atomicAdd(&g_cnt[0][vi], vadj);
        atomicAdd(&g_cnt[1][ai], aadj);
    }
}

// ---------------- sequential EMA count normalization ----------------
__global__ void k_ec(const float* __restrict__ ema_count) {
    __shared__ float sb[MC];
    int t = threadIdx.x;
    float ec = DECAYC * ema_count[t] + (1.f - DECAYC) * g_cnt[0][t];
    sb[t] = ec; __syncthreads();
    for (int o = 512; o > 0; o >>= 1) { if (t < o) sb[t] += sb[t + o]; __syncthreads(); }
    float n1 = sb[0]; __syncthreads();
    ec = (ec + EPSC) / (n1 + MC * EPSC) * n1;
    ec = DECAYC * ec + (1.f - DECAYC) * g_cnt[1][t];
    sb[t] = ec; __syncthreads();
    for (int o = 512; o > 0; o >>= 1) { if (t < o) sb[t] += sb[t + o]; __syncthreads(); }
    float n2 = sb[0]; __syncthreads();
    g_ec[t] = (ec + EPSC) / (n2 + MC * EPSC) * n2;
}

// ---------------- normalized new codebook -> fp16 g_Bh directly ----------------
__global__ void k_en(const float* __restrict__ ema_weight) {
    __shared__ float sb[256];
    int m = blockIdx.x, t = threadIdx.x;
    float ew = (DECAYC * DECAYC) * ema_weight[(size_t)m * DK + t]
             + DECAYC * 0.5f * (1.f - DECAYC) * g_wsum[0][m][t]
             + 0.5f * (1.f - DECAYC) * g_wsum[1][m][t];
    float emb = ew / g_ec[m];
    sb[t] = emb * emb; __syncthreads();
    for (int o = 128; o > 0; o >>= 1) { if (t < o) sb[t] += sb[t + o]; __syncthreads(); }
    float nrm = sqrtf(sb[0]);
    g_Bh[m][t] = __float2half(emb / fmaxf(nrm, 1e-8f));
}

// ---------------- combine per-row partials into scaled loss (writes d_out) ----------------
__global__ void k_loss(float* __restrict__ out) {
    __shared__ float sp[8];
    int t = threadIdx.x, lane = t & 31, w = t >> 5;
    int row = blockIdx.x * 256 + t, z = blockIdx.y;
    float c = __logf(g_esum[z][row])
            - COMMITC * g_pick[z][0][row]
            - (1.f - COMMITC) * g_pick[z][1][row];
#pragma unroll
    for (int o = 16; o; o >>= 1) c += __shfl_xor_sync(0xFFFFFFFFu, c, o);
    if (lane == 0) sp[w] = c;
    __syncthreads();
    if (t == 0) {
        float acc = 0.f;
#pragma unroll
        for (int i = 0; i < 8; i++) acc += sp[i];
        atomicAdd(out, acc * (COMMITC / ((float)NTOK * (float)BV)));
    }
}

extern "C" void kernel_launch(void* const* d_in, const int* in_sizes, int n_in,
                              void* d_out, int out_size) {
    const float* audio      = (const float*)d_in[0];
    const float* video      = (const float*)d_in[1];
    const float* emb        = (const float*)d_in[2];
    const float* ema_count  = (const float*)d_in[3];
    const float* ema_weight = (const float*)d_in[4];
    float* out = (float*)d_out;

    cudaFuncSetAttribute(k_mmaD, cudaFuncAttributeMaxDynamicSharedMemorySize, SMEMSZ);
    cudaFuncSetAttribute(k_mmaL, cudaFuncAttributeMaxDynamicSharedMemorySize, SMEMSZ);

    k_zero<<<2048, 256>>>(out);
    k_prepA<<<dim3(NTOK, 2), 256>>>(audio, video);
    k_prepB<<<MC, 256>>>(emb);

    dim3 gg(MC / BN, NTOK / BM, 2);
    k_mmaD<<<gg, 256, SMEMSZ>>>();                    // phase 1: fused dist moments
    k_scatter<<<NTOK, 256>>>(audio, video);           // combine adj/idx + EMA scatter
    k_ec<<<1, MC>>>(ema_count);
    k_en<<<MC, 256>>>(ema_weight);                    // new codebook -> fp16 directly
    k_mmaL<<<gg, 256, SMEMSZ>>>();                    // phase 2: fused logits partials
    k_loss<<<dim3(NTOK / 256, 2), 256>>>(out);
}

// round 13
// speedup vs baseline: 6.4392x; 1.0075x over previous
#include <cuda_runtime.h>
#include <cuda_fp16.h>
#include <cstdint>

#define NTOK 16384
#define DK   256
#define MC   1024
#define BV   32
#define COMMITC 0.25f
#define DECAYC  0.99f
#define EPSC    1e-5f
#define TEMPC   0.1f
#define LOGM    6.931471805599453f   /* ln(1024) */
#define EPSM    (EPSC * (float)MC)             /* 0.01024 */
#define C2T     (0.5f * EPSC * EPSC)           /* 5e-11 */

// ---------------- static device scratch ----------------
__device__ __half g_Ah[2][NTOK][DK];       // fp16 hi of A (audio/video)
__device__ __half g_Bh[MC][DK];            // fp16 hi of B (emb, then en)
__device__ float g_xsq[2][NTOK];
__device__ float g_esq[MC];
__device__ int   g_idx[2][NTOK];
__device__ float g_cnt[2][MC];
__device__ float g_wsum[2][MC][DK];
__device__ float g_ec[MC];
// fused phase-1 per-row partials: power sums S1,S2 of s' and packed argmax key
__device__ float g_S1[2][NTOK];
__device__ float g_S2[2][NTOK];
__device__ unsigned int g_key[2][NTOK];
// fused phase-2 per-row partials
__device__ float g_esum[2][NTOK];

// ---------------- PTX helpers (sm_80-family only; no arch-'a' features) ----------------
__device__ __forceinline__ uint32_t smem_u32(const void* p) {
    uint32_t a;
    asm("{ .reg .u64 t; cvta.to.shared.u64 t, %1; cvt.u32.u64 %0, t; }" : "=r"(a) : "l"(p));
    return a;
}
#define CP_ASYNC16(dst, src) \
    asm volatile("cp.async.cg.shared.global [%0], [%1], 16;" :: "r"(dst), "l"(src) : "memory")
#define CP_COMMIT() asm volatile("cp.async.commit_group;" ::: "memory")
#define CP_WAIT(n)  asm volatile("cp.async.wait_group %0;" :: "n"(n) : "memory")

__device__ __forceinline__ void ldsm_x4(uint32_t* r, uint32_t addr) {
    asm volatile("ldmatrix.sync.aligned.m8n8.x4.shared.b16 {%0,%1,%2,%3}, [%4];"
        : "=r"(r[0]), "=r"(r[1]), "=r"(r[2]), "=r"(r[3]) : "r"(addr));
}
__device__ __forceinline__ void mma16816(float* d, const uint32_t* a,
                                         uint32_t b0, uint32_t b1) {
    asm volatile("mma.sync.aligned.m16n8k16.row.col.f32.f16.f16.f32 "
        "{%0,%1,%2,%3}, {%4,%5,%6,%7}, {%8,%9}, {%0,%1,%2,%3};"
        : "+f"(d[0]), "+f"(d[1]), "+f"(d[2]), "+f"(d[3])
        : "r"(a[0]), "r"(a[1]), "r"(a[2]), "r"(a[3]), "r"(b0), "r"(b1));
}

// ---------------- zero accumulators (every launch, graph replay) ----------------
__global__ void k_zero(float* __restrict__ out) {
    unsigned i = blockIdx.x * blockDim.x + threadIdx.x;
    if (i < 2u * MC * DK) ((float*)g_wsum)[i] = 0.f;
    if (i < 2u * MC)      ((float*)g_cnt)[i]  = 0.f;
    if (i < 2u * NTOK) {
        ((float*)g_esum)[i] = 0.f;
        ((float*)g_S1)[i] = 0.f;
        ((float*)g_S2)[i] = 0.f;
        ((unsigned int*)g_key)[i] = 0u;
    }
    if (i == 0) out[0] = 0.f;
}

// ---------------- prep A: fp16 hi + row squared norm ----------------
__global__ void k_prepA(const float* __restrict__ a, const float* __restrict__ v) {
    int row = blockIdx.x, z = blockIdx.y, t = threadIdx.x;
    int lane = t & 31, w = t >> 5;
    const float* src = (z ? v : a) + (size_t)row * DK;
    float x = src[t];
    g_Ah[z][row][t] = __float2half(x);
    __shared__ float sp[8];
    float s = x * x;
#pragma unroll
    for (int o = 16; o; o >>= 1) s += __shfl_xor_sync(0xFFFFFFFFu, s, o);
    if (lane == 0) sp[w] = s;
    __syncthreads();
    if (t == 0) {
        float acc = 0.f;
#pragma unroll
        for (int i = 0; i < 8; i++) acc += sp[i];
        g_xsq[z][row] = acc;
    }
}

// ---------------- prep B (phase 1 only): fp16 hi + esq ----------------
__global__ void k_prepB(const float* __restrict__ embParam) {
    int m = blockIdx.x, t = threadIdx.x;
    int lane = t & 31, w = t >> 5;
    float x = embParam[(size_t)m * DK + t];
    g_Bh[m][t] = __float2half(x);
    __shared__ float sp[8];
    float s = x * x;
#pragma unroll
    for (int o = 16; o; o >>= 1) s += __shfl_xor_sync(0xFFFFFFFFu, s, o);
    if (lane == 0) sp[w] = s;
    __syncthreads();
    if (t == 0) {
        float acc = 0.f;
#pragma unroll
        for (int i = 0; i < 8; i++) acc += sp[i];
        g_esq[m] = acc;
    }
}

// ---------------- shared HMMA mainloop (CTA 128x128, K=256, 4 chunks of 64) ----------------
#define BM 128
#define BN 128
#define BK 64
#define NCH 4
#define STAGE (BM * BK * 2 + BN * BK * 2)  /* 32768 */
#define NSTAGE 3
#define SMEMSZ (NSTAGE * STAGE)            /* 98304 */

// All B frags for a k-step are loaded BEFORE any MMA consumes them: breaks the
// LDSM->HMMA short-scoreboard chain (6 independent LDSMs in flight).
#define MMA_MAINLOOP(Ag, Bg)                                                     \
    auto load_stage = [&](int s, int c) {                                        \
        uint32_t ab = sb + s * STAGE;                                            \
        uint32_t bb = ab + BM * BK * 2;                                          \
        _Pragma("unroll")                                                        \
        for (int j = 0; j < 4; ++j) {                                            \
            int idx = t + j * 256, row = idx >> 3, blk = idx & 7;                \
            CP_ASYNC16(ab + row * 128 + 16 * (blk ^ (row & 7)),                  \
                       (Ag) + (size_t)row * DK + c * BK + blk * 8);              \
        }                                                                        \
        _Pragma("unroll")                                                        \
        for (int j = 0; j < 4; ++j) {                                            \
            int idx = t + j * 256, row = idx >> 3, blk = idx & 7;                \
            CP_ASYNC16(bb + row * 128 + 16 * (blk ^ (row & 7)),                  \
                       (Bg) + (size_t)row * DK + c * BK + blk * 8);              \
        }                                                                        \
        CP_COMMIT();                                                             \
    };                                                                           \
    load_stage(0, 0);                                                            \
    load_stage(1, 1);                                                            \
    const int wm = w >> 1, wn = w & 1;                                           \
    const uint32_t swz = (uint32_t)(lane & 7) << 4;                              \
    const uint32_t kh  = (uint32_t)(lane & 16);                                  \
    const uint32_t rA  = wm * 32 + (lane & 15);                                  \
    const uint32_t rB  = wn * 64 + (lane & 15);                                  \
    _Pragma("unroll 1")                                                          \
    for (int c = 0; c < NCH; ++c) {                                              \
        if (c == NCH - 1) { CP_WAIT(0); } else { CP_WAIT(1); }                   \
        __syncthreads();                                                         \
        if (c + 2 < NCH) load_stage((c + 2) % NSTAGE, c + 2);                    \
        uint32_t ab = sb + (c % NSTAGE) * STAGE;                                 \
        uint32_t bb = ab + BM * BK * 2;                                          \
        _Pragma("unroll")                                                        \
        for (int ks = 0; ks < 4; ++ks) {                                         \
            uint32_t kx = ((uint32_t)(ks * 32) + kh) ^ swz;                      \
            uint32_t A0[4], A1[4], Bf[4][4];                                     \
            ldsm_x4(A0, ab + rA * 128 + kx);                                     \
            ldsm_x4(A1, ab + (rA + 16) * 128 + kx);                              \
            _Pragma("unroll")                                                    \
            for (int q = 0; q < 4; ++q)                                          \
                ldsm_x4(Bf[q], bb + (rB + q * 16) * 128 + kx);                   \
            _Pragma("unroll")                                                    \
            for (int q = 0; q < 4; ++q) {                                        \
                mma16816(acc[0][2 * q],     A0, Bf[q][0], Bf[q][2]);             \
                mma16816(acc[0][2 * q + 1], A0, Bf[q][1], Bf[q][3]);             \
                mma16816(acc[1][2 * q],     A1, Bf[q][0], Bf[q][2]);             \
                mma16816(acc[1][2 * q + 1], A1, Bf[q][1], Bf[q][3]);             \
            }                                                                    \
        }                                                                        \
    }

// ---------------- phase-1 GEMM, epilogue accumulates S1,S2 of s' + argmax ----------------
// s' = sqrt(xs) - sqrt(dist), |s'| <= ||e|| <= ~0.04 (Cauchy-Schwarz).
// 2nd-order moments suffice: delta on adj ~5e-5 relative.
__global__ void __launch_bounds__(256, 2) k_mmaD() {
    extern __shared__ char sm[];
    const uint32_t sb = smem_u32(sm);
    const int t = threadIdx.x, lane = t & 31, w = t >> 5;
    const int z = blockIdx.z;
    const int bm = blockIdx.y * BM, bn = blockIdx.x * BN;
    const __half* Ag = &g_Ah[z][bm][0];
    const __half* Bg = &g_Bh[bn][0];

    float acc[2][8][4];
#pragma unroll
    for (int i = 0; i < 2; i++)
#pragma unroll
        for (int j = 0; j < 8; j++)
#pragma unroll
            for (int k = 0; k < 4; k++) acc[i][j][k] = 0.f;

    MMA_MAINLOOP(Ag, Bg)

    const int bnw = bn + wn * 64 + (lane & 3) * 2;
#pragma unroll
    for (int mi = 0; mi < 2; ++mi) {
#pragma unroll
        for (int h = 0; h < 2; ++h) {
            int r = bm + wm * 32 + mi * 16 + h * 8 + (lane >> 2);
            float xs = g_xsq[z][r];
            float sq = sqrtf(xs);
            float s1 = 0.f, s2 = 0.f;
            float bs = -1e30f; int bc = 0;
#pragma unroll
            for (int j = 0; j < 8; ++j) {
                int col = bnw + j * 8;
#pragma unroll
                for (int e = 0; e < 2; ++e) {
                    float S = acc[mi][j][2 * h + e];
                    float dist = fmaxf(fmaf(-2.f, S, xs + g_esq[col + e]), 0.f);
                    float sp = sq - sqrtf(dist);
                    s1 += sp;
                    s2 = fmaf(sp, sp, s2);
                    if (sp > bs) { bs = sp; bc = col + e; }
                }
            }
            // 32-bit argmax key: larger s' wins, tie -> smaller index.
            float bsc = fminf(fmaxf(bs, -0.06f), 0.0624f) + 1.0f;
            uint32_t key = ((__float_as_uint(bsc) - 0x3F700000u) << 10)
                         | (uint32_t)(MC - 1 - bc);
#pragma unroll
            for (int o = 1; o <= 2; o <<= 1) {
                s1 += __shfl_xor_sync(0xFFFFFFFFu, s1, o);
                s2 += __shfl_xor_sync(0xFFFFFFFFu, s2, o);
                uint32_t ok = __shfl_xor_sync(0xFFFFFFFFu, key, o);
                key = (ok > key) ? ok : key;
            }
            if ((lane & 3) == 0) {
                atomicAdd(&g_S1[z][r], s1);
                atomicAdd(&g_S2[z][r], s2);
                atomicMax(&g_key[z][r], key);
            }
        }
    }
}

// ---------------- phase-2 GEMM with fused sum-exp epilogue (no pick logic) ----------------
__global__ void __launch_bounds__(256, 2) k_mmaL() {
    extern __shared__ char sm[];
    const uint32_t sb = smem_u32(sm);
    const int t = threadIdx.x, lane = t & 31, w = t >> 5;
    const int z = blockIdx.z;
    const int bm = blockIdx.y * BM, bn = blockIdx.x * BN;
    const __half* Ag = &g_Ah[z][bm][0];
    const __half* Bg = &g_Bh[bn][0];

    float acc[2][8][4];
#pragma unroll
    for (int i = 0; i < 2; i++)
#pragma unroll
        for (int j = 0; j < 8; j++)
#pragma unroll
            for (int k = 0; k < 4; k++) acc[i][j][k] = 0.f;

    MMA_MAINLOOP(Ag, Bg)

#pragma unroll
    for (int mi = 0; mi < 2; ++mi) {
#pragma unroll
        for (int h = 0; h < 2; ++h) {
            int r = bm + wm * 32 + mi * 16 + h * 8 + (lane >> 2);
            float xs = g_xsq[z][r];
            float scale = 1.f / (fmaxf(sqrtf(xs), 1e-8f) * TEMPC);
            float rowsum = 0.f;
#pragma unroll
            for (int j = 0; j < 8; ++j) {
                rowsum += __expf(acc[mi][j][2 * h]     * scale)
                        + __expf(acc[mi][j][2 * h + 1] * scale);
            }
            rowsum += __shfl_xor_sync(0xFFFFFFFFu, rowsum, 1);
            rowsum += __shfl_xor_sync(0xFFFFFFFFu, rowsum, 2);
            if ((lane & 3) == 0) atomicAdd(&g_esum[z][r], rowsum);
        }
    }
}

// ---------------- EMA scatter (+ per-row adj/idx combine from moments) ----------------
// logM - H = -log(Z/M) + W/Z + M*eps - (eps^2/2) Z*U1, with 2nd-order moments:
// Z = M+S1+S2/2, W = S1+S2, U1 = M-S1+S2/2.
__global__ void k_scatter(const float* __restrict__ a, const float* __restrict__ v) {
    __shared__ float sadj[2];
    __shared__ int   sidx[2];
    int row = blockIdx.x, t = threadIdx.x;
    if (t < 2) {
        int z = t;
        float s1 = g_S1[z][row], s2 = g_S2[z][row];
        float Z  = (float)MC + s1 + 0.5f * s2;
        float W  = s1 + s2;
        float U1 = (float)MC - s1 + 0.5f * s2;
        float D  = EPSM + W / Z - __logf(Z * (1.0f / MC)) - C2T * Z * U1;
        sadj[z] = D * (1.0f / LOGM);
        int idx = MC - 1 - (int)(g_key[z][row] & 1023u);
        sidx[z] = idx;
        g_idx[z][row] = idx;
    }
    __syncthreads();
    int   ai = sidx[0], vi = sidx[1];
    float aadj = sadj[0], vadj = sadj[1];
    float tv = a[(size_t)row * DK + t] + v[(size_t)row * DK + t];
    atomicAdd(&g_wsum[0][vi][t], vadj * tv);
    atomicAdd(&g_wsum[1][ai][t], aadj * tv);
    if (t == 0) {
        atomicAdd(&g_cnt[0][vi], vadj);
        atomicAdd(&g_cnt[1][ai], aadj);
    }
}

// ---------------- sequential EMA count normalization (shuffle reductions) ----------------
__global__ void k_ec(const float* __restrict__ ema_count) {
    __shared__ float sp[32];
    __shared__ float stot;
    int t = threadIdx.x, lane = t & 31, w = t >> 5;
    float ec = DECAYC * ema_count[t] + (1.f - DECAYC) * g_cnt[0][t];
    float s = ec;
#pragma unroll
    for (int o = 16; o; o >>= 1) s += __shfl_xor_sync(0xFFFFFFFFu, s, o);
    if (lane == 0) sp[w] = s;
    __syncthreads();
    if (t < 32) {
        float v = sp[t];
#pragma unroll
        for (int o = 16; o; o >>= 1) v += __shfl_xor_sync(0xFFFFFFFFu, v, o);
        if (t == 0) stot = v;
    }
    __syncthreads();
    float n1 = stot;
    ec = (ec + EPSC) / (n1 + MC * EPSC) * n1;
    ec = DECAYC * ec + (1.f - DECAYC) * g_cnt[1][t];
    s = ec;
#pragma unroll
    for (int o = 16; o; o >>= 1) s += __shfl_xor_sync(0xFFFFFFFFu, s, o);
    if (lane == 0) sp[w] = s;
    __syncthreads();
    if (t < 32) {
        float v = sp[t];
#pragma unroll
        for (int o = 16; o; o >>= 1) v += __shfl_xor_sync(0xFFFFFFFFu, v, o);
        if (t == 0) stot = v;
    }
    __syncthreads();
    float n2 = stot;
    g_ec[t] = (ec + EPSC) / (n2 + MC * EPSC) * n2;
}

// ---------------- normalized new codebook -> fp16 g_Bh directly ----------------
__global__ void k_en(const float* __restrict__ ema_weight) {
    __shared__ float sb[256];
    int m = blockIdx.x, t = threadIdx.x;
    float ew = (DECAYC * DECAYC) * ema_weight[(size_t)m * DK + t]
             + DECAYC * 0.5f * (1.f - DECAYC) * g_wsum[0][m][t]
             + 0.5f * (1.f - DECAYC) * g_wsum[1][m][t];
    float emb = ew / g_ec[m];
    sb[t] = emb * emb; __syncthreads();
    for (int o = 128; o > 0; o >>= 1) { if (t < o) sb[t] += sb[t + o]; __syncthreads(); }
    float nrm = sqrtf(sb[0]);
    g_Bh[m][t] = __float2half(emb / fmaxf(nrm, 1e-8f));
}

// ---------------- per-row loss: recompute self/cross logits as fp16 dots ----------------
// warp per (z,row): picks = dot(x_h, en_h)/(||x||*T), then c = log(esum) - mix(picks).
__global__ void k_loss(float* __restrict__ out) {
    __shared__ float sp[8];
    int t = threadIdx.x, lane = t & 31, w = t >> 5;
    int row = blockIdx.x * 8 + w, z = blockIdx.y;

    int selfI  = g_idx[z][row];
    int crossI = g_idx[1 - z][row];
    const uint4* xr = (const uint4*)&g_Ah[z][row][0];
    const uint4* es = (const uint4*)&g_Bh[selfI][0];
    const uint4* ec = (const uint4*)&g_Bh[crossI][0];
    uint4 xv = xr[lane], sv = es[lane], cv = ec[lane];
    float ds = 0.f, dc = 0.f;
    const __half2* xh = (const __half2*)&xv;
    const __half2* sh = (const __half2*)&sv;
    const __half2* ch = (const __half2*)&cv;
#pragma unroll
    for (int i = 0; i < 4; ++i) {
        float2 xf = __half22float2(xh[i]);
        float2 sf = __half22float2(sh[i]);
        float2 cf = __half22float2(ch[i]);
        ds = fmaf(xf.x, sf.x, fmaf(xf.y, sf.y, ds));
        dc = fmaf(xf.x, cf.x, fmaf(xf.y, cf.y, dc));
    }
#pragma unroll
    for (int o = 16; o; o >>= 1) {
        ds += __shfl_xor_sync(0xFFFFFFFFu, ds, o);
        dc += __shfl_xor_sync(0xFFFFFFFFu, dc, o);
    }
    if (lane == 0) {
        float scale = 1.f / (fmaxf(sqrtf(g_xsq[z][row]), 1e-8f) * TEMPC);
        sp[w] = __logf(g_esum[z][row])
              - COMMITC * (ds * scale) - (1.f - COMMITC) * (dc * scale);
    }
    __syncthreads();
    if (t == 0) {
        float acc = 0.f;
#pragma unroll
        for (int i = 0; i < 8; i++) acc += sp[i];
        atomicAdd(out, acc * (COMMITC / ((float)NTOK * (float)BV)));
    }
}

extern "C" void kernel_launch(void* const* d_in, const int* in_sizes, int n_in,
                              void* d_out, int out_size) {
    const float* audio      = (const float*)d_in[0];
    const float* video      = (const float*)d_in[1];
    const float* emb        = (const float*)d_in[2];
    const float* ema_count  = (const float*)d_in[3];
    const float* ema_weight = (const float*)d_in[4];
    float* out = (float*)d_out;

    cudaFuncSetAttribute(k_mmaD, cudaFuncAttributeMaxDynamicSharedMemorySize, SMEMSZ);
    cudaFuncSetAttribute(k_mmaL, cudaFuncAttributeMaxDynamicSharedMemorySize, SMEMSZ);

    k_zero<<<2048, 256>>>(out);
    k_prepA<<<dim3(NTOK, 2), 256>>>(audio, video);
    k_prepB<<<MC, 256>>>(emb);

    dim3 gg(MC / BN, NTOK / BM, 2);
    k_mmaD<<<gg, 256, SMEMSZ>>>();                    // phase 1: fused dist moments
    k_scatter<<<NTOK, 256>>>(audio, video);           // combine adj/idx + EMA scatter
    k_ec<<<1, MC>>>(ema_count);
    k_en<<<MC, 256>>>(ema_weight);                    // new codebook -> fp16 directly
    k_mmaL<<<gg, 256, SMEMSZ>>>();                    // phase 2: fused sum-exp partials
    k_loss<<<dim3(NTOK / 8, 2), 256>>>(out);
}